// round 2
// baseline (speedup 1.0000x reference)
#include <cuda_runtime.h>

#define BB 8
#define TT 2304
#define CC 512
#define HS 48
#define HH 64
#define NN 8
#define MM (BB*TT)
#define BTC (MM*CC)

// ---------------- scratch (device globals; no allocation allowed) ----------------
__device__ float g_xx[2*BTC];   // conv-shift delta, per direction, sequence order
__device__ float g_r [2*BTC];
__device__ float g_k [2*BTC];
__device__ float g_v [2*BTC];
__device__ float g_d [2*BTC];   // decay exp(-exp(w))
__device__ float g_y [2*BTC];   // wkv outputs per direction
__device__ float g_ln[BTC];     // combined + layernormed

__device__ __forceinline__ float4 ld4(const float* p) { return *(const float4*)p; }

// ---------------- conv shift: xx = (alpha-weighted multi-scale conv - identity) ----------------
// Merged 1x1/3x3/5x5 depthwise convs into a single 5x5 coefficient stencil per channel.
// dir=0: image (u=y rows, q=x cols), x index (u+o1)*48 + (q+o2)
// dir=1: transposed image (u=w rows, q=h cols), x index (q+o2)*48 + (u+o1)
__global__ void conv_shift_kernel(const float* __restrict__ x,
                                  const float* __restrict__ c1,
                                  const float* __restrict__ c3,
                                  const float* __restrict__ c5,
                                  const float* __restrict__ alpha)
{
    const int u   = blockIdx.x;
    const int b   = blockIdx.y;
    const int dir = blockIdx.z;
    const int lc  = threadIdx.x & 127;
    const int qh  = threadIdx.x >> 7;
    const float a0 = alpha[0], a1 = alpha[1], a2 = alpha[2], a3 = alpha[3];
    const float* xb = x + (size_t)b*TT*CC;
    float* xxb = g_xx + (size_t)dir*BTC + (size_t)b*TT*CC;

    for (int c0 = 0; c0 < CC; c0 += 128) {
        const int c = c0 + lc;
        float coef[5][5];
        #pragma unroll
        for (int i = 0; i < 5; ++i) {
            #pragma unroll
            for (int j = 0; j < 5; ++j) {
                float w = a3 * c5[c*25 + i*5 + j];
                if (i >= 1 && i <= 3 && j >= 1 && j <= 3)
                    w += a2 * c3[c*9 + (i-1)*3 + (j-1)];
                if (i == 2 && j == 2)
                    w += a1 * c1[c] + a0 - 1.0f;   // -1: xx = sh - x
                coef[i][j] = w;
            }
        }
        for (int q = qh; q < HS; q += 2) {
            float acc = 0.0f;
            #pragma unroll
            for (int i = 0; i < 5; ++i) {
                const int uu = u + i - 2;
                if (uu < 0 || uu >= HS) continue;
                #pragma unroll
                for (int j = 0; j < 5; ++j) {
                    const int qq = q + j - 2;
                    if (qq < 0 || qq >= HS) continue;
                    const int idx = dir ? (qq*HS + uu) : (uu*HS + qq);
                    acc = fmaf(coef[i][j], xb[(size_t)idx*CC + c], acc);
                }
            }
            xxb[(size_t)(u*HS + q)*CC + c] = acc;
        }
    }
}

// ---------------- decay: d = exp(-exp(time_decay + tanh(xw @ w1) @ w2)) ----------------
__global__ void decay_kernel(const float* __restrict__ x,
                             const float* __restrict__ maa_w,
                             const float* __restrict__ tdec,
                             const float* __restrict__ w1,   // [C][16]
                             const float* __restrict__ w2)   // [16][C]
{
    const int t = blockIdx.x, b = blockIdx.y, dir = blockIdx.z;
    const int m = b*TT + t;
    const int row = dir ? (b*TT + (t % HS)*HS + (t / HS)) : m;
    const int tid = threadIdx.x;   // 128
    float p[16];
    #pragma unroll
    for (int j = 0; j < 16; ++j) p[j] = 0.0f;
    #pragma unroll
    for (int i = 0; i < 4; ++i) {
        const int c = tid + i*128;
        const float v = x[(size_t)row*CC + c]
                      + g_xx[(size_t)dir*BTC + (size_t)m*CC + c] * maa_w[c];
        const float4* wr4 = (const float4*)(w1 + c*16);
        const float4 wa = wr4[0], wb = wr4[1], wc = wr4[2], wd = wr4[3];
        p[0]  = fmaf(v, wa.x, p[0]);  p[1]  = fmaf(v, wa.y, p[1]);
        p[2]  = fmaf(v, wa.z, p[2]);  p[3]  = fmaf(v, wa.w, p[3]);
        p[4]  = fmaf(v, wb.x, p[4]);  p[5]  = fmaf(v, wb.y, p[5]);
        p[6]  = fmaf(v, wb.z, p[6]);  p[7]  = fmaf(v, wb.w, p[7]);
        p[8]  = fmaf(v, wc.x, p[8]);  p[9]  = fmaf(v, wc.y, p[9]);
        p[10] = fmaf(v, wc.z, p[10]); p[11] = fmaf(v, wc.w, p[11]);
        p[12] = fmaf(v, wd.x, p[12]); p[13] = fmaf(v, wd.y, p[13]);
        p[14] = fmaf(v, wd.z, p[14]); p[15] = fmaf(v, wd.w, p[15]);
    }
    #pragma unroll
    for (int j = 0; j < 16; ++j) {
        #pragma unroll
        for (int off = 16; off > 0; off >>= 1)
            p[j] += __shfl_xor_sync(0xffffffffu, p[j], off);
    }
    __shared__ float ps[4][16];
    __shared__ float th[16];
    if ((tid & 31) == 0) {
        #pragma unroll
        for (int j = 0; j < 16; ++j) ps[tid >> 5][j] = p[j];
    }
    __syncthreads();
    if (tid < 16) th[tid] = tanhf(ps[0][tid] + ps[1][tid] + ps[2][tid] + ps[3][tid]);
    __syncthreads();
    #pragma unroll
    for (int i = 0; i < 4; ++i) {
        const int c = tid + i*128;
        float wv = tdec[c];
        #pragma unroll
        for (int j = 0; j < 16; ++j) wv = fmaf(th[j], w2[j*CC + c], wv);
        g_d[(size_t)dir*BTC + (size_t)m*CC + c] = expf(-expf(wv));
    }
}

// ---------------- fp32 GEMM: Out[m][n] = sum_k A[m][k] * W[n][k] ----------------
// A[m][k] = X[rowmap(m)][k] (+ g_xx[dir][m][k]*maa[k] when use_xx)
// out_sel: 0 -> g_r+dir, 1 -> g_k+dir, 2 -> g_v+dir, 3 -> Out_ext
// src_ln:  0 -> X_ext, 1 -> g_ln
// 128x128 tile, K-chunks of 16, register-prefetch double buffering, 8x8 microtile.
__global__ __launch_bounds__(256)
void gemm_kernel(const float* __restrict__ X_ext,
                 const float* __restrict__ maa,
                 const float* __restrict__ W,
                 float* __restrict__ Out_ext,
                 int src_ln, int use_xx, int out_sel, int dir)
{
    __shared__ float As[16*132];
    __shared__ float Bs[16*132];
    const int tid = threadIdx.x;
    const int bn = blockIdx.x * 128;
    const int bm = blockIdx.y * 128;

    const float* X = src_ln ? g_ln : X_ext;
    float* Out;
    switch (out_sel) {
        case 0: Out = g_r + (size_t)dir*BTC; break;
        case 1: Out = g_k + (size_t)dir*BTC; break;
        case 2: Out = g_v + (size_t)dir*BTC; break;
        default: Out = Out_ext; break;
    }

    const int ml = tid >> 1;            // row staged by this thread
    const int kl = (tid & 1) * 8;       // k-offset (8 floats) staged by this thread
    const int mA = bm + ml;
    int xr;
    if (dir) { const int t = mA % TT, bq = mA / TT; xr = bq*TT + (t % HS)*HS + (t / HS); }
    else xr = mA;
    const int nB = bn + ml;

    const float* px  = X + (size_t)xr*CC + kl;
    const float* pxx = use_xx ? (g_xx + (size_t)dir*BTC + (size_t)mA*CC + kl) : (const float*)0;
    const float* pm  = maa ? (maa + kl) : (const float*)0;
    const float* pw  = W + (size_t)nB*CC + kl;

    const int ty8 = (tid >> 4) * 8;
    const int tx8 = (tid & 15) * 8;

    float acc[8][8];
    #pragma unroll
    for (int i = 0; i < 8; ++i)
        #pragma unroll
        for (int j = 0; j < 8; ++j) acc[i][j] = 0.0f;

    float4 a0p, a1p, b0p, b1p;
    // prefetch chunk 0
    {
        a0p = ld4(px); a1p = ld4(px + 4);
        if (pxx) {
            const float4 q0 = ld4(pxx), q1 = ld4(pxx + 4);
            const float4 m0 = ld4(pm),  m1 = ld4(pm + 4);
            a0p.x = fmaf(q0.x, m0.x, a0p.x); a0p.y = fmaf(q0.y, m0.y, a0p.y);
            a0p.z = fmaf(q0.z, m0.z, a0p.z); a0p.w = fmaf(q0.w, m0.w, a0p.w);
            a1p.x = fmaf(q1.x, m1.x, a1p.x); a1p.y = fmaf(q1.y, m1.y, a1p.y);
            a1p.z = fmaf(q1.z, m1.z, a1p.z); a1p.w = fmaf(q1.w, m1.w, a1p.w);
        }
        b0p = ld4(pw); b1p = ld4(pw + 4);
    }

    for (int kc = 0; kc < 32; ++kc) {
        __syncthreads();
        {
            float* ap = &As[kl*132 + ml];
            ap[0*132] = a0p.x; ap[1*132] = a0p.y; ap[2*132] = a0p.z; ap[3*132] = a0p.w;
            ap[4*132] = a1p.x; ap[5*132] = a1p.y; ap[6*132] = a1p.z; ap[7*132] = a1p.w;
            float* bp = &Bs[kl*132 + ml];
            bp[0*132] = b0p.x; bp[1*132] = b0p.y; bp[2*132] = b0p.z; bp[3*132] = b0p.w;
            bp[4*132] = b1p.x; bp[5*132] = b1p.y; bp[6*132] = b1p.z; bp[7*132] = b1p.w;
        }
        __syncthreads();
        if (kc < 31) {
            const int o = (kc + 1) * 16;
            a0p = ld4(px + o); a1p = ld4(px + o + 4);
            if (pxx) {
                const float4 q0 = ld4(pxx + o), q1 = ld4(pxx + o + 4);
                const float4 m0 = ld4(pm + o),  m1 = ld4(pm + o + 4);
                a0p.x = fmaf(q0.x, m0.x, a0p.x); a0p.y = fmaf(q0.y, m0.y, a0p.y);
                a0p.z = fmaf(q0.z, m0.z, a0p.z); a0p.w = fmaf(q0.w, m0.w, a0p.w);
                a1p.x = fmaf(q1.x, m1.x, a1p.x); a1p.y = fmaf(q1.y, m1.y, a1p.y);
                a1p.z = fmaf(q1.z, m1.z, a1p.z); a1p.w = fmaf(q1.w, m1.w, a1p.w);
            }
            b0p = ld4(pw + o); b1p = ld4(pw + o + 4);
        }
        #pragma unroll
        for (int k = 0; k < 16; ++k) {
            const float4 aA = ld4(&As[k*132 + ty8]);
            const float4 aB = ld4(&As[k*132 + ty8 + 4]);
            const float4 bA = ld4(&Bs[k*132 + tx8]);
            const float4 bB = ld4(&Bs[k*132 + tx8 + 4]);
            const float av[8] = {aA.x,aA.y,aA.z,aA.w,aB.x,aB.y,aB.z,aB.w};
            const float bv[8] = {bA.x,bA.y,bA.z,bA.w,bB.x,bB.y,bB.z,bB.w};
            #pragma unroll
            for (int i = 0; i < 8; ++i)
                #pragma unroll
                for (int j = 0; j < 8; ++j)
                    acc[i][j] = fmaf(av[i], bv[j], acc[i][j]);
        }
    }

    #pragma unroll
    for (int i = 0; i < 8; ++i) {
        float* po = Out + (size_t)(bm + ty8 + i)*CC + bn + tx8;
        *(float4*)po       = make_float4(acc[i][0], acc[i][1], acc[i][2], acc[i][3]);
        *(float4*)(po + 4) = make_float4(acc[i][4], acc[i][5], acc[i][6], acc[i][7]);
    }
}

// ---------------- WKV6 scan ----------------
// 16 lanes per (dir,b,h) head: lane = p*8+j, p in {0,1} owns i-half, j the output col.
// State S[i][j] in 4 registers per lane. y_j = sum_i r_i*(S_ij + u_i k_i v_j);
// S_ij = d_i S_ij + k_i v_j. Cross-half reduce via one shfl_xor(8).
__global__ void wkv_scan_kernel(const float* __restrict__ u)
{
    const int g = blockIdx.x * 32 + threadIdx.x;   // blockDim = 32
    const int s = g & 15;
    const int j = s & 7, p = s >> 3;
    const int head = g >> 4;                       // 0..1023
    const int h = head & (HH-1);
    const int b = (head >> 6) & (BB-1);
    const int dir = head >> 9;
    const int i0 = p * 4;

    const float4 uu = ld4(u + h*NN + i0);
    const size_t base = (size_t)dir*BTC + (size_t)(b*TT)*CC + h*NN;
    const float* rr = g_r + base;
    const float* kk = g_k + base;
    const float* vv = g_v + base;
    const float* dd = g_d + base;
    float* yy = g_y + base;

    float S0 = 0.f, S1 = 0.f, S2 = 0.f, S3 = 0.f;
    int off = 0;
    #pragma unroll 2
    for (int t = 0; t < TT; ++t, off += CC) {
        const float4 r4 = ld4(rr + off + i0);
        const float4 k4 = ld4(kk + off + i0);
        const float4 d4 = ld4(dd + off + i0);
        const float v = vv[off + j];
        float y = 0.f, kv, tt;
        kv = k4.x*v; tt = fmaf(uu.x, kv, S0); y = fmaf(r4.x, tt, y); S0 = fmaf(d4.x, S0, kv);
        kv = k4.y*v; tt = fmaf(uu.y, kv, S1); y = fmaf(r4.y, tt, y); S1 = fmaf(d4.y, S1, kv);
        kv = k4.z*v; tt = fmaf(uu.z, kv, S2); y = fmaf(r4.z, tt, y); S2 = fmaf(d4.z, S2, kv);
        kv = k4.w*v; tt = fmaf(uu.w, kv, S3); y = fmaf(r4.w, tt, y); S3 = fmaf(d4.w, S3, kv);
        y += __shfl_xor_sync(0xffffffffu, y, 8);
        if (p == 0) yy[off + j] = y;
    }
}

// ---------------- combine directions + layernorm ----------------
__global__ void combine_ln_kernel(const float* __restrict__ lng,
                                  const float* __restrict__ lnb)
{
    const int t = blockIdx.x, b = blockIdx.y;
    const int tid = threadIdx.x;   // 128
    const int y = t / HS, xq = t % HS;
    const int tcol = xq*HS + y;    // col-direction sequence position mapping to (y,x)
    const float* yr = g_y + (size_t)(b*TT + t)*CC;
    const float* yc = g_y + (size_t)BTC + (size_t)(b*TT + tcol)*CC;
    float o[4];
    float s = 0.f, sq = 0.f;
    #pragma unroll
    for (int i = 0; i < 4; ++i) {
        const int c = tid + i*128;
        const float v = 0.5f*(yr[c] + yc[c]);
        o[i] = v; s += v; sq += v*v;
    }
    #pragma unroll
    for (int off = 16; off > 0; off >>= 1) {
        s  += __shfl_xor_sync(0xffffffffu, s,  off);
        sq += __shfl_xor_sync(0xffffffffu, sq, off);
    }
    __shared__ float ss[4], sqs[4];
    if ((tid & 31) == 0) { ss[tid >> 5] = s; sqs[tid >> 5] = sq; }
    __syncthreads();
    s  = ss[0] + ss[1] + ss[2] + ss[3];
    sq = sqs[0] + sqs[1] + sqs[2] + sqs[3];
    const float mu = s * (1.0f/CC);
    const float var = sq * (1.0f/CC) - mu*mu;
    const float rstd = rsqrtf(var + 1e-5f);
    float* outp = g_ln + (size_t)(b*TT + t)*CC;
    #pragma unroll
    for (int i = 0; i < 4; ++i) {
        const int c = tid + i*128;
        outp[c] = (o[i] - mu)*rstd*lng[c] + lnb[c];
    }
}

// ---------------- launch ----------------
extern "C" void kernel_launch(void* const* d_in, const int* in_sizes, int n_in,
                              void* d_out, int out_size)
{
    (void)in_sizes; (void)n_in; (void)out_size;
    const float* x     = (const float*)d_in[0];
    // d_in[1] = Hs, d_in[2] = Ws (compile-time constants here)
    const float* c1    = (const float*)d_in[3];
    const float* c3    = (const float*)d_in[4];
    const float* c5    = (const float*)d_in[5];
    const float* alpha = (const float*)d_in[6];
    const float* maa_w = (const float*)d_in[7];
    const float* maa_k = (const float*)d_in[8];
    const float* maa_v = (const float*)d_in[9];
    const float* maa_r = (const float*)d_in[10];
    const float* tdec  = (const float*)d_in[11];
    const float* w1    = (const float*)d_in[12];
    const float* w2    = (const float*)d_in[13];
    const float* uu    = (const float*)d_in[14];
    const float* Wr    = (const float*)d_in[15];
    const float* Wk    = (const float*)d_in[16];
    const float* Wv    = (const float*)d_in[17];
    const float* Wo    = (const float*)d_in[18];
    const float* lng   = (const float*)d_in[19];
    const float* lnb   = (const float*)d_in[20];

    conv_shift_kernel<<<dim3(HS, BB, 2), 256>>>(x, c1, c3, c5, alpha);
    decay_kernel<<<dim3(TT, BB, 2), 128>>>(x, maa_w, tdec, w1, w2);

    const dim3 ggrid(CC/128, MM/128);   // (4, 144)
    for (int dir = 0; dir < 2; ++dir) {
        gemm_kernel<<<ggrid, 256>>>(x, maa_r, Wr, nullptr, 0, 1, 0, dir);
        gemm_kernel<<<ggrid, 256>>>(x, maa_k, Wk, nullptr, 0, 1, 1, dir);
        gemm_kernel<<<ggrid, 256>>>(x, maa_v, Wv, nullptr, 0, 1, 2, dir);
    }

    wkv_scan_kernel<<<512, 32>>>(uu);
    combine_ln_kernel<<<dim3(TT, BB), 128>>>(lng, lnb);
    gemm_kernel<<<ggrid, 256>>>(nullptr, nullptr, Wo, (float*)d_out, 1, 0, 3, 0);
}

// round 3
// speedup vs baseline: 1.0897x; 1.0897x over previous
#include <cuda_runtime.h>
#include <cstdint>

#define BB 8
#define TT 2304
#define CC 512
#define HS 48
#define HH 64
#define NN 8
#define MM (BB*TT)
#define BTC (MM*CC)

// ---------------- scratch (device globals; no allocation allowed) ----------------
__device__ float g_xx[2*BTC];   // conv-shift delta, per direction, sequence order
__device__ float g_r [2*BTC];
__device__ float g_k [2*BTC];
__device__ float g_v [2*BTC];
__device__ float g_d [2*BTC];   // decay exp(-exp(w))
__device__ float g_y [2*BTC];   // wkv outputs per direction
__device__ float g_ln[BTC];     // combined + layernormed

__device__ __forceinline__ float4 ld4(const float* p) { return *(const float4*)p; }

__device__ __forceinline__ uint32_t f2tf32(float f) {
    uint32_t r;
    asm("cvt.rna.tf32.f32 %0, %1;" : "=r"(r) : "f"(f));
    return r;
}

// ---------------- conv shift ----------------
__global__ void conv_shift_kernel(const float* __restrict__ x,
                                  const float* __restrict__ c1,
                                  const float* __restrict__ c3,
                                  const float* __restrict__ c5,
                                  const float* __restrict__ alpha)
{
    const int u   = blockIdx.x;
    const int b   = blockIdx.y;
    const int dir = blockIdx.z;
    const int lc  = threadIdx.x & 127;
    const int qh  = threadIdx.x >> 7;
    const float a0 = alpha[0], a1 = alpha[1], a2 = alpha[2], a3 = alpha[3];
    const float* xb = x + (size_t)b*TT*CC;
    float* xxb = g_xx + (size_t)dir*BTC + (size_t)b*TT*CC;

    for (int c0 = 0; c0 < CC; c0 += 128) {
        const int c = c0 + lc;
        float coef[5][5];
        #pragma unroll
        for (int i = 0; i < 5; ++i) {
            #pragma unroll
            for (int j = 0; j < 5; ++j) {
                float w = a3 * c5[c*25 + i*5 + j];
                if (i >= 1 && i <= 3 && j >= 1 && j <= 3)
                    w += a2 * c3[c*9 + (i-1)*3 + (j-1)];
                if (i == 2 && j == 2)
                    w += a1 * c1[c] + a0 - 1.0f;
                coef[i][j] = w;
            }
        }
        for (int q = qh; q < HS; q += 2) {
            float acc = 0.0f;
            #pragma unroll
            for (int i = 0; i < 5; ++i) {
                const int uu = u + i - 2;
                if (uu < 0 || uu >= HS) continue;
                #pragma unroll
                for (int j = 0; j < 5; ++j) {
                    const int qq = q + j - 2;
                    if (qq < 0 || qq >= HS) continue;
                    const int idx = dir ? (qq*HS + uu) : (uu*HS + qq);
                    acc = fmaf(coef[i][j], xb[(size_t)idx*CC + c], acc);
                }
            }
            xxb[(size_t)(u*HS + q)*CC + c] = acc;
        }
    }
}

// ---------------- decay ----------------
__global__ void decay_kernel(const float* __restrict__ x,
                             const float* __restrict__ maa_w,
                             const float* __restrict__ tdec,
                             const float* __restrict__ w1,
                             const float* __restrict__ w2)
{
    const int t = blockIdx.x, b = blockIdx.y, dir = blockIdx.z;
    const int m = b*TT + t;
    const int row = dir ? (b*TT + (t % HS)*HS + (t / HS)) : m;
    const int tid = threadIdx.x;   // 128
    float p[16];
    #pragma unroll
    for (int j = 0; j < 16; ++j) p[j] = 0.0f;
    #pragma unroll
    for (int i = 0; i < 4; ++i) {
        const int c = tid + i*128;
        const float v = x[(size_t)row*CC + c]
                      + g_xx[(size_t)dir*BTC + (size_t)m*CC + c] * maa_w[c];
        const float4* wr4 = (const float4*)(w1 + c*16);
        const float4 wa = wr4[0], wb = wr4[1], wc = wr4[2], wd = wr4[3];
        p[0]  = fmaf(v, wa.x, p[0]);  p[1]  = fmaf(v, wa.y, p[1]);
        p[2]  = fmaf(v, wa.z, p[2]);  p[3]  = fmaf(v, wa.w, p[3]);
        p[4]  = fmaf(v, wb.x, p[4]);  p[5]  = fmaf(v, wb.y, p[5]);
        p[6]  = fmaf(v, wb.z, p[6]);  p[7]  = fmaf(v, wb.w, p[7]);
        p[8]  = fmaf(v, wc.x, p[8]);  p[9]  = fmaf(v, wc.y, p[9]);
        p[10] = fmaf(v, wc.z, p[10]); p[11] = fmaf(v, wc.w, p[11]);
        p[12] = fmaf(v, wd.x, p[12]); p[13] = fmaf(v, wd.y, p[13]);
        p[14] = fmaf(v, wd.z, p[14]); p[15] = fmaf(v, wd.w, p[15]);
    }
    #pragma unroll
    for (int j = 0; j < 16; ++j) {
        #pragma unroll
        for (int off = 16; off > 0; off >>= 1)
            p[j] += __shfl_xor_sync(0xffffffffu, p[j], off);
    }
    __shared__ float ps[4][16];
    __shared__ float th[16];
    if ((tid & 31) == 0) {
        #pragma unroll
        for (int j = 0; j < 16; ++j) ps[tid >> 5][j] = p[j];
    }
    __syncthreads();
    if (tid < 16) th[tid] = tanhf(ps[0][tid] + ps[1][tid] + ps[2][tid] + ps[3][tid]);
    __syncthreads();
    #pragma unroll
    for (int i = 0; i < 4; ++i) {
        const int c = tid + i*128;
        float wv = tdec[c];
        #pragma unroll
        for (int j = 0; j < 16; ++j) wv = fmaf(th[j], w2[j*CC + c], wv);
        g_d[(size_t)dir*BTC + (size_t)m*CC + c] = expf(-expf(wv));
    }
}

// ---------------- 3xTF32 tensor-core GEMM: Out[m][n] = sum_k A[m][k] * W[n][k] ----------------
// A[m][k] = X[rowmap(m)][k] (+ g_xx[dir][m][k]*maa[k] when use_xx)
// 128x128 tile, BK=16, 8 warps (warp tile 64x32), hi/lo tf32 planes in smem.
#define AST 20   // smem row stride (floats): (4r+c)-style conflict-free for mma frag loads

__global__ __launch_bounds__(256)
void gemm_kernel(const float* __restrict__ X_ext,
                 const float* __restrict__ maa,
                 const float* __restrict__ W,
                 float* __restrict__ Out_ext,
                 int src_ln, int use_xx, int out_sel, int dir)
{
    __shared__ uint32_t As_hi[128*AST], As_lo[128*AST];
    __shared__ uint32_t Bs_hi[128*AST], Bs_lo[128*AST];

    const int tid = threadIdx.x;
    const int bn = blockIdx.x * 128;
    const int bm = blockIdx.y * 128;

    const float* X = src_ln ? g_ln : X_ext;
    float* Out;
    switch (out_sel) {
        case 0: Out = g_r + (size_t)dir*BTC; break;
        case 1: Out = g_k + (size_t)dir*BTC; break;
        case 2: Out = g_v + (size_t)dir*BTC; break;
        default: Out = Out_ext; break;
    }

    // ---- staging geometry: 2 float4 per thread per tile (A and B each) ----
    int srow[2], sc4[2];
    const float* pxA[2];
    const float* pxx[2];
    const float* pwB[2];
    #pragma unroll
    for (int i = 0; i < 2; ++i) {
        const int f4id = tid + i*256;
        srow[i] = f4id >> 2;          // 0..127
        sc4[i]  = (f4id & 3) * 4;     // 0,4,8,12
        const int mA = bm + srow[i];
        int xr;
        if (dir) { const int t = mA % TT, bq = mA / TT; xr = bq*TT + (t % HS)*HS + (t / HS); }
        else xr = mA;
        pxA[i] = X + (size_t)xr*CC + sc4[i];
        pxx[i] = use_xx ? (g_xx + (size_t)dir*BTC + (size_t)mA*CC + sc4[i]) : (const float*)0;
        pwB[i] = W + (size_t)(bn + srow[i])*CC + sc4[i];
    }

    const int lane = tid & 31;
    const int grp  = lane >> 2;       // 0..7
    const int qid  = lane & 3;        // 0..3
    const int wid  = tid >> 5;
    const int wm   = wid >> 2;        // 0..1 -> 64 rows
    const int wn   = wid & 3;         // 0..3 -> 32 cols

    float c[4][4][4];
    #pragma unroll
    for (int mt = 0; mt < 4; ++mt)
        #pragma unroll
        for (int nt = 0; nt < 4; ++nt)
            #pragma unroll
            for (int e = 0; e < 4; ++e) c[mt][nt][e] = 0.0f;

    float4 aP[2], bP[2];
    // prefetch ktile 0
    #pragma unroll
    for (int i = 0; i < 2; ++i) {
        aP[i] = ld4(pxA[i]);
        if (use_xx) {
            const float4 q = ld4(pxx[i]);
            const float4 m4 = ld4(maa + sc4[i]);
            aP[i].x = fmaf(q.x, m4.x, aP[i].x); aP[i].y = fmaf(q.y, m4.y, aP[i].y);
            aP[i].z = fmaf(q.z, m4.z, aP[i].z); aP[i].w = fmaf(q.w, m4.w, aP[i].w);
        }
        bP[i] = ld4(pwB[i]);
    }

    for (int kt = 0; kt < 32; ++kt) {
        __syncthreads();
        // ---- transform + STS hi/lo planes ----
        #pragma unroll
        for (int i = 0; i < 2; ++i) {
            const int ad = srow[i]*AST + sc4[i];
            uint4 h, l;
            h.x = f2tf32(aP[i].x); l.x = f2tf32(aP[i].x - __uint_as_float(h.x));
            h.y = f2tf32(aP[i].y); l.y = f2tf32(aP[i].y - __uint_as_float(h.y));
            h.z = f2tf32(aP[i].z); l.z = f2tf32(aP[i].z - __uint_as_float(h.z));
            h.w = f2tf32(aP[i].w); l.w = f2tf32(aP[i].w - __uint_as_float(h.w));
            *(uint4*)&As_hi[ad] = h; *(uint4*)&As_lo[ad] = l;
            h.x = f2tf32(bP[i].x); l.x = f2tf32(bP[i].x - __uint_as_float(h.x));
            h.y = f2tf32(bP[i].y); l.y = f2tf32(bP[i].y - __uint_as_float(h.y));
            h.z = f2tf32(bP[i].z); l.z = f2tf32(bP[i].z - __uint_as_float(h.z));
            h.w = f2tf32(bP[i].w); l.w = f2tf32(bP[i].w - __uint_as_float(h.w));
            *(uint4*)&Bs_hi[ad] = h; *(uint4*)&Bs_lo[ad] = l;
        }
        __syncthreads();
        // ---- prefetch next ktile ----
        if (kt < 31) {
            const int o = (kt + 1) * 16;
            #pragma unroll
            for (int i = 0; i < 2; ++i) {
                aP[i] = ld4(pxA[i] + o);
                if (use_xx) {
                    const float4 q = ld4(pxx[i] + o);
                    const float4 m4 = ld4(maa + o + sc4[i]);
                    aP[i].x = fmaf(q.x, m4.x, aP[i].x); aP[i].y = fmaf(q.y, m4.y, aP[i].y);
                    aP[i].z = fmaf(q.z, m4.z, aP[i].z); aP[i].w = fmaf(q.w, m4.w, aP[i].w);
                }
                bP[i] = ld4(pwB[i] + o);
            }
        }
        // ---- 2 k8-steps of mma ----
        #pragma unroll
        for (int ks = 0; ks < 2; ++ks) {
            const int kk = ks*8 + qid;
            uint32_t ah[4][4], al[4][4];
            #pragma unroll
            for (int mt = 0; mt < 4; ++mt) {
                const int base = (wm*64 + mt*16 + grp)*AST + kk;
                ah[mt][0] = As_hi[base];           al[mt][0] = As_lo[base];
                ah[mt][1] = As_hi[base + 8*AST];   al[mt][1] = As_lo[base + 8*AST];
                ah[mt][2] = As_hi[base + 4];       al[mt][2] = As_lo[base + 4];
                ah[mt][3] = As_hi[base + 8*AST+4]; al[mt][3] = As_lo[base + 8*AST+4];
            }
            uint32_t bh[4][2], bl[4][2];
            #pragma unroll
            for (int nt = 0; nt < 4; ++nt) {
                const int base = (wn*32 + nt*8 + grp)*AST + kk;
                bh[nt][0] = Bs_hi[base];     bl[nt][0] = Bs_lo[base];
                bh[nt][1] = Bs_hi[base + 4]; bl[nt][1] = Bs_lo[base + 4];
            }
            #pragma unroll
            for (int mt = 0; mt < 4; ++mt) {
                #pragma unroll
                for (int nt = 0; nt < 4; ++nt) {
                    asm volatile(
                        "mma.sync.aligned.m16n8k8.row.col.f32.tf32.tf32.f32 "
                        "{%0,%1,%2,%3}, {%4,%5,%6,%7}, {%8,%9}, {%0,%1,%2,%3};"
                        : "+f"(c[mt][nt][0]), "+f"(c[mt][nt][1]),
                          "+f"(c[mt][nt][2]), "+f"(c[mt][nt][3])
                        : "r"(ah[mt][0]), "r"(ah[mt][1]), "r"(ah[mt][2]), "r"(ah[mt][3]),
                          "r"(bh[nt][0]), "r"(bh[nt][1]));
                    asm volatile(
                        "mma.sync.aligned.m16n8k8.row.col.f32.tf32.tf32.f32 "
                        "{%0,%1,%2,%3}, {%4,%5,%6,%7}, {%8,%9}, {%0,%1,%2,%3};"
                        : "+f"(c[mt][nt][0]), "+f"(c[mt][nt][1]),
                          "+f"(c[mt][nt][2]), "+f"(c[mt][nt][3])
                        : "r"(al[mt][0]), "r"(al[mt][1]), "r"(al[mt][2]), "r"(al[mt][3]),
                          "r"(bh[nt][0]), "r"(bh[nt][1]));
                    asm volatile(
                        "mma.sync.aligned.m16n8k8.row.col.f32.tf32.tf32.f32 "
                        "{%0,%1,%2,%3}, {%4,%5,%6,%7}, {%8,%9}, {%0,%1,%2,%3};"
                        : "+f"(c[mt][nt][0]), "+f"(c[mt][nt][1]),
                          "+f"(c[mt][nt][2]), "+f"(c[mt][nt][3])
                        : "r"(ah[mt][0]), "r"(ah[mt][1]), "r"(ah[mt][2]), "r"(ah[mt][3]),
                          "r"(bl[nt][0]), "r"(bl[nt][1]));
                }
            }
        }
    }

    // ---- epilogue: C frag layout -> global ----
    #pragma unroll
    for (int mt = 0; mt < 4; ++mt) {
        const int row = bm + wm*64 + mt*16 + grp;
        #pragma unroll
        for (int nt = 0; nt < 4; ++nt) {
            const int col = bn + wn*32 + nt*8 + qid*2;
            *(float2*)(Out + (size_t)row*CC + col)     = make_float2(c[mt][nt][0], c[mt][nt][1]);
            *(float2*)(Out + (size_t)(row+8)*CC + col) = make_float2(c[mt][nt][2], c[mt][nt][3]);
        }
    }
}

// ---------------- WKV6 scan ----------------
__global__ void wkv_scan_kernel(const float* __restrict__ u)
{
    const int g = blockIdx.x * 32 + threadIdx.x;   // blockDim = 32
    const int s = g & 15;
    const int j = s & 7, p = s >> 3;
    const int head = g >> 4;                       // 0..1023
    const int h = head & (HH-1);
    const int b = (head >> 6) & (BB-1);
    const int dir = head >> 9;
    const int i0 = p * 4;

    const float4 uu = ld4(u + h*NN + i0);
    const size_t base = (size_t)dir*BTC + (size_t)(b*TT)*CC + h*NN;
    const float* rr = g_r + base;
    const float* kk = g_k + base;
    const float* vv = g_v + base;
    const float* dd = g_d + base;
    float* yy = g_y + base;

    float S0 = 0.f, S1 = 0.f, S2 = 0.f, S3 = 0.f;
    int off = 0;
    #pragma unroll 2
    for (int t = 0; t < TT; ++t, off += CC) {
        const float4 r4 = ld4(rr + off + i0);
        const float4 k4 = ld4(kk + off + i0);
        const float4 d4 = ld4(dd + off + i0);
        const float v = vv[off + j];
        float y = 0.f, kv, tt;
        kv = k4.x*v; tt = fmaf(uu.x, kv, S0); y = fmaf(r4.x, tt, y); S0 = fmaf(d4.x, S0, kv);
        kv = k4.y*v; tt = fmaf(uu.y, kv, S1); y = fmaf(r4.y, tt, y); S1 = fmaf(d4.y, S1, kv);
        kv = k4.z*v; tt = fmaf(uu.z, kv, S2); y = fmaf(r4.z, tt, y); S2 = fmaf(d4.z, S2, kv);
        kv = k4.w*v; tt = fmaf(uu.w, kv, S3); y = fmaf(r4.w, tt, y); S3 = fmaf(d4.w, S3, kv);
        y += __shfl_xor_sync(0xffffffffu, y, 8);
        if (p == 0) yy[off + j] = y;
    }
}

// ---------------- combine directions + layernorm ----------------
__global__ void combine_ln_kernel(const float* __restrict__ lng,
                                  const float* __restrict__ lnb)
{
    const int t = blockIdx.x, b = blockIdx.y;
    const int tid = threadIdx.x;   // 128
    const int y = t / HS, xq = t % HS;
    const int tcol = xq*HS + y;
    const float* yr = g_y + (size_t)(b*TT + t)*CC;
    const float* yc = g_y + (size_t)BTC + (size_t)(b*TT + tcol)*CC;
    float o[4];
    float s = 0.f, sq = 0.f;
    #pragma unroll
    for (int i = 0; i < 4; ++i) {
        const int c = tid + i*128;
        const float v = 0.5f*(yr[c] + yc[c]);
        o[i] = v; s += v; sq += v*v;
    }
    #pragma unroll
    for (int off = 16; off > 0; off >>= 1) {
        s  += __shfl_xor_sync(0xffffffffu, s,  off);
        sq += __shfl_xor_sync(0xffffffffu, sq, off);
    }
    __shared__ float ss[4], sqs[4];
    if ((tid & 31) == 0) { ss[tid >> 5] = s; sqs[tid >> 5] = sq; }
    __syncthreads();
    s  = ss[0] + ss[1] + ss[2] + ss[3];
    sq = sqs[0] + sqs[1] + sqs[2] + sqs[3];
    const float mu = s * (1.0f/CC);
    const float var = sq * (1.0f/CC) - mu*mu;
    const float rstd = rsqrtf(var + 1e-5f);
    float* outp = g_ln + (size_t)(b*TT + t)*CC;
    #pragma unroll
    for (int i = 0; i < 4; ++i) {
        const int c = tid + i*128;
        outp[c] = (o[i] - mu)*rstd*lng[c] + lnb[c];
    }
}

// ---------------- launch ----------------
extern "C" void kernel_launch(void* const* d_in, const int* in_sizes, int n_in,
                              void* d_out, int out_size)
{
    (void)in_sizes; (void)n_in; (void)out_size;
    const float* x     = (const float*)d_in[0];
    const float* c1    = (const float*)d_in[3];
    const float* c3    = (const float*)d_in[4];
    const float* c5    = (const float*)d_in[5];
    const float* alpha = (const float*)d_in[6];
    const float* maa_w = (const float*)d_in[7];
    const float* maa_k = (const float*)d_in[8];
    const float* maa_v = (const float*)d_in[9];
    const float* maa_r = (const float*)d_in[10];
    const float* tdec  = (const float*)d_in[11];
    const float* w1    = (const float*)d_in[12];
    const float* w2    = (const float*)d_in[13];
    const float* uu    = (const float*)d_in[14];
    const float* Wr    = (const float*)d_in[15];
    const float* Wk    = (const float*)d_in[16];
    const float* Wv    = (const float*)d_in[17];
    const float* Wo    = (const float*)d_in[18];
    const float* lng   = (const float*)d_in[19];
    const float* lnb   = (const float*)d_in[20];

    conv_shift_kernel<<<dim3(HS, BB, 2), 256>>>(x, c1, c3, c5, alpha);
    decay_kernel<<<dim3(TT, BB, 2), 128>>>(x, maa_w, tdec, w1, w2);

    const dim3 ggrid(CC/128, MM/128);   // (4, 144)
    for (int dir = 0; dir < 2; ++dir) {
        gemm_kernel<<<ggrid, 256>>>(x, maa_r, Wr, nullptr, 0, 1, 0, dir);
        gemm_kernel<<<ggrid, 256>>>(x, maa_k, Wk, nullptr, 0, 1, 1, dir);
        gemm_kernel<<<ggrid, 256>>>(x, maa_v, Wv, nullptr, 0, 1, 2, dir);
    }

    wkv_scan_kernel<<<512, 32>>>(uu);
    combine_ln_kernel<<<dim3(TT, BB), 128>>>(lng, lnb);
    gemm_kernel<<<ggrid, 256>>>(nullptr, nullptr, Wo, (float*)d_out, 1, 0, 3, 0);
}

// round 4
// speedup vs baseline: 2.3928x; 2.1958x over previous
#include <cuda_runtime.h>
#include <cuda_bf16.h>
#include <cstdint>

#define BB 8
#define TT 2304
#define CC 512
#define HS 48
#define HH 64
#define NN 8
#define MM (BB*TT)
#define BTC (MM*CC)
#define NCHUNK 24
#define CLEN 96          // TT / NCHUNK
#define NUNIT 1024       // 2 * BB * HH

// ---------------- scratch (device globals) ----------------
__device__ float g_xx[2*BTC];
__device__ float g_r [2*BTC];
__device__ float g_k [2*BTC];
__device__ float g_v [2*BTC];
__device__ float g_d [2*BTC];
__device__ float g_y [2*BTC];
// bf16 hi/lo planes: A variants 0..5 = dir*3 + {r,k,v}; 6 = layernormed
__device__ uint16_t g_Ahi[7*(size_t)BTC];
__device__ uint16_t g_Alo[7*(size_t)BTC];
__device__ uint16_t g_Whi[4*CC*CC];   // 0=Wr 1=Wk 2=Wv 3=Wo
__device__ uint16_t g_Wlo[4*CC*CC];
// chunked scan scratch
__device__ float g_M [NUNIT*NCHUNK*64];
__device__ float g_P [NUNIT*NCHUNK*8];
__device__ float g_S0[NUNIT*NCHUNK*64];

__device__ __forceinline__ float4 ld4(const float* p) { return *(const float4*)p; }

__device__ __forceinline__ void bfsplit4(float4 v, uint2& hi, uint2& lo) {
    __nv_bfloat16 hx = __float2bfloat16(v.x);
    __nv_bfloat16 hy = __float2bfloat16(v.y);
    __nv_bfloat16 hz = __float2bfloat16(v.z);
    __nv_bfloat16 hw = __float2bfloat16(v.w);
    float rx = v.x - __bfloat162float(hx);
    float ry = v.y - __bfloat162float(hy);
    float rz = v.z - __bfloat162float(hz);
    float rw = v.w - __bfloat162float(hw);
    __nv_bfloat16 lx = __float2bfloat16(rx);
    __nv_bfloat16 ly = __float2bfloat16(ry);
    __nv_bfloat16 lz = __float2bfloat16(rz);
    __nv_bfloat16 lw = __float2bfloat16(rw);
    hi.x = ((uint32_t)__bfloat16_as_ushort(hy) << 16) | __bfloat16_as_ushort(hx);
    hi.y = ((uint32_t)__bfloat16_as_ushort(hw) << 16) | __bfloat16_as_ushort(hz);
    lo.x = ((uint32_t)__bfloat16_as_ushort(ly) << 16) | __bfloat16_as_ushort(lx);
    lo.y = ((uint32_t)__bfloat16_as_ushort(lw) << 16) | __bfloat16_as_ushort(lz);
}

// ---------------- conv shift ----------------
__global__ void conv_shift_kernel(const float* __restrict__ x,
                                  const float* __restrict__ c1,
                                  const float* __restrict__ c3,
                                  const float* __restrict__ c5,
                                  const float* __restrict__ alpha)
{
    const int u   = blockIdx.x;
    const int b   = blockIdx.y;
    const int dir = blockIdx.z;
    const int lc  = threadIdx.x & 127;
    const int qh  = threadIdx.x >> 7;
    const float a0 = alpha[0], a1 = alpha[1], a2 = alpha[2], a3 = alpha[3];
    const float* xb = x + (size_t)b*TT*CC;
    float* xxb = g_xx + (size_t)dir*BTC + (size_t)b*TT*CC;

    for (int c0 = 0; c0 < CC; c0 += 128) {
        const int c = c0 + lc;
        float coef[5][5];
        #pragma unroll
        for (int i = 0; i < 5; ++i) {
            #pragma unroll
            for (int j = 0; j < 5; ++j) {
                float w = a3 * c5[c*25 + i*5 + j];
                if (i >= 1 && i <= 3 && j >= 1 && j <= 3)
                    w += a2 * c3[c*9 + (i-1)*3 + (j-1)];
                if (i == 2 && j == 2)
                    w += a1 * c1[c] + a0 - 1.0f;
                coef[i][j] = w;
            }
        }
        for (int q = qh; q < HS; q += 2) {
            float acc = 0.0f;
            #pragma unroll
            for (int i = 0; i < 5; ++i) {
                const int uu = u + i - 2;
                if (uu < 0 || uu >= HS) continue;
                #pragma unroll
                for (int j = 0; j < 5; ++j) {
                    const int qq = q + j - 2;
                    if (qq < 0 || qq >= HS) continue;
                    const int idx = dir ? (qq*HS + uu) : (uu*HS + qq);
                    acc = fmaf(coef[i][j], xb[(size_t)idx*CC + c], acc);
                }
            }
            xxb[(size_t)(u*HS + q)*CC + c] = acc;
        }
    }
}

// ---------------- decay ----------------
__global__ void decay_kernel(const float* __restrict__ x,
                             const float* __restrict__ maa_w,
                             const float* __restrict__ tdec,
                             const float* __restrict__ w1,
                             const float* __restrict__ w2)
{
    const int t = blockIdx.x, b = blockIdx.y, dir = blockIdx.z;
    const int m = b*TT + t;
    const int row = dir ? (b*TT + (t % HS)*HS + (t / HS)) : m;
    const int tid = threadIdx.x;   // 128
    float p[16];
    #pragma unroll
    for (int j = 0; j < 16; ++j) p[j] = 0.0f;
    #pragma unroll
    for (int i = 0; i < 4; ++i) {
        const int c = tid + i*128;
        const float v = x[(size_t)row*CC + c]
                      + g_xx[(size_t)dir*BTC + (size_t)m*CC + c] * maa_w[c];
        const float4* wr4 = (const float4*)(w1 + c*16);
        const float4 wa = wr4[0], wb = wr4[1], wc = wr4[2], wd = wr4[3];
        p[0]  = fmaf(v, wa.x, p[0]);  p[1]  = fmaf(v, wa.y, p[1]);
        p[2]  = fmaf(v, wa.z, p[2]);  p[3]  = fmaf(v, wa.w, p[3]);
        p[4]  = fmaf(v, wb.x, p[4]);  p[5]  = fmaf(v, wb.y, p[5]);
        p[6]  = fmaf(v, wb.z, p[6]);  p[7]  = fmaf(v, wb.w, p[7]);
        p[8]  = fmaf(v, wc.x, p[8]);  p[9]  = fmaf(v, wc.y, p[9]);
        p[10] = fmaf(v, wc.z, p[10]); p[11] = fmaf(v, wc.w, p[11]);
        p[12] = fmaf(v, wd.x, p[12]); p[13] = fmaf(v, wd.y, p[13]);
        p[14] = fmaf(v, wd.z, p[14]); p[15] = fmaf(v, wd.w, p[15]);
    }
    #pragma unroll
    for (int j = 0; j < 16; ++j) {
        #pragma unroll
        for (int off = 16; off > 0; off >>= 1)
            p[j] += __shfl_xor_sync(0xffffffffu, p[j], off);
    }
    __shared__ float ps[4][16];
    __shared__ float th[16];
    if ((tid & 31) == 0) {
        #pragma unroll
        for (int j = 0; j < 16; ++j) ps[tid >> 5][j] = p[j];
    }
    __syncthreads();
    if (tid < 16) th[tid] = tanhf(ps[0][tid] + ps[1][tid] + ps[2][tid] + ps[3][tid]);
    __syncthreads();
    #pragma unroll
    for (int i = 0; i < 4; ++i) {
        const int c = tid + i*128;
        float wv = tdec[c];
        #pragma unroll
        for (int j = 0; j < 16; ++j) wv = fmaf(th[j], w2[j*CC + c], wv);
        g_d[(size_t)dir*BTC + (size_t)m*CC + c] = expf(-expf(wv));
    }
}

// ---------------- prep: W -> bf16 hi/lo planes ----------------
__global__ void prep_w_kernel(const float* __restrict__ Wr, const float* __restrict__ Wk,
                              const float* __restrict__ Wv, const float* __restrict__ Wo)
{
    const int idx = blockIdx.x*256 + threadIdx.x;       // over 4*CC*CC/4
    const int w = idx / (CC*CC/4);
    const int r = idx % (CC*CC/4);
    const float* W = (w==0) ? Wr : (w==1) ? Wk : (w==2) ? Wv : Wo;
    float4 v = ld4(W + (size_t)r*4);
    uint2 hi, lo;
    bfsplit4(v, hi, lo);
    ((uint2*)(g_Whi + (size_t)w*CC*CC))[r] = hi;
    ((uint2*)(g_Wlo + (size_t)w*CC*CC))[r] = lo;
}

// ---------------- prep: A variants (x[perm] + xx*maa) -> bf16 hi/lo planes ----------------
__global__ void prep_a_kernel(const float* __restrict__ x,
                              const float* __restrict__ maar,
                              const float* __restrict__ maak,
                              const float* __restrict__ maav,
                              int dir)
{
    const int idx = blockIdx.x*256 + threadIdx.x;       // over MM*CC/4
    const int m  = idx >> 7;
    const int c4 = (idx & 127) * 4;
    int xr;
    if (dir) { const int t = m % TT, bq = m / TT; xr = bq*TT + (t % HS)*HS + (t / HS); }
    else xr = m;
    const float4 xv  = ld4(x + (size_t)xr*CC + c4);
    const float4 xxv = ld4(g_xx + (size_t)dir*BTC + (size_t)m*CC + c4);
    const float* maas[3] = {maar, maak, maav};
    #pragma unroll
    for (int v = 0; v < 3; ++v) {
        const float4 mv = ld4(maas[v] + c4);
        float4 a;
        a.x = fmaf(xxv.x, mv.x, xv.x);
        a.y = fmaf(xxv.y, mv.y, xv.y);
        a.z = fmaf(xxv.z, mv.z, xv.z);
        a.w = fmaf(xxv.w, mv.w, xv.w);
        uint2 hi, lo;
        bfsplit4(a, hi, lo);
        const size_t vb = (size_t)(dir*3 + v) * BTC;
        ((uint2*)(g_Ahi + vb))[idx] = hi;
        ((uint2*)(g_Alo + vb))[idx] = lo;
    }
}

// ---------------- bf16-split tensor-core GEMM: Out[m][n] = sum_k A[m][k]*W[n][k] ----------------
#define STRD 12
#define PLANE_W (128*STRD)          // u32 per plane
#define PLANE_B (PLANE_W*4)         // 6144 bytes
#define STAGE_B (PLANE_B*4)         // 24576 bytes

__device__ __forceinline__ void cp16(uint32_t dst, const void* src) {
    asm volatile("cp.async.cg.shared.global [%0], [%1], 16;\n" :: "r"(dst), "l"(src));
}

__global__ __launch_bounds__(256)
void gemm_bf16_kernel(float* __restrict__ Out_ext, int a_sel, int w_sel, int out_sel, int dir)
{
    __shared__ uint32_t sm[2][4][PLANE_W];   // [stage][Ahi,Alo,Bhi,Blo]

    const int tid = threadIdx.x;
    const int bn = blockIdx.x * 128;
    const int bm = blockIdx.y * 128;

    const uint16_t* Ah = g_Ahi + (size_t)a_sel*BTC;
    const uint16_t* Al = g_Alo + (size_t)a_sel*BTC;
    const uint16_t* Bh = g_Whi + (size_t)w_sel*CC*CC;
    const uint16_t* Bl = g_Wlo + (size_t)w_sel*CC*CC;
    float* Out;
    switch (out_sel) {
        case 0: Out = g_r + (size_t)dir*BTC; break;
        case 1: Out = g_k + (size_t)dir*BTC; break;
        case 2: Out = g_v + (size_t)dir*BTC; break;
        default: Out = Out_ext; break;
    }

    // staging: each thread copies one 16B chunk per plane per ktile
    const int row  = tid >> 1;
    const int half = tid & 1;
    const uint16_t* pa_h = Ah + (size_t)(bm + row)*CC + half*8;
    const uint16_t* pa_l = Al + (size_t)(bm + row)*CC + half*8;
    const uint16_t* pb_h = Bh + (size_t)(bn + row)*CC + half*8;
    const uint16_t* pb_l = Bl + (size_t)(bn + row)*CC + half*8;
    const uint32_t smbase = (uint32_t)__cvta_generic_to_shared(&sm[0][0][0]);
    const uint32_t doff = (uint32_t)(row*STRD + half*4) * 4;

    const int lane = tid & 31;
    const int grp  = lane >> 2;
    const int qid  = lane & 3;
    const int wid  = tid >> 5;
    const int wm   = wid >> 2;
    const int wn   = wid & 3;

    float c[4][4][4];
    #pragma unroll
    for (int mt = 0; mt < 4; ++mt)
        #pragma unroll
        for (int nt = 0; nt < 4; ++nt)
            #pragma unroll
            for (int e = 0; e < 4; ++e) c[mt][nt][e] = 0.0f;

    // prefetch ktiles 0 and 1
    #pragma unroll
    for (int kt = 0; kt < 2; ++kt) {
        const int off = kt*16;
        const uint32_t d = smbase + kt*STAGE_B + doff;
        cp16(d + 0*PLANE_B, pa_h + off);
        cp16(d + 1*PLANE_B, pa_l + off);
        cp16(d + 2*PLANE_B, pb_h + off);
        cp16(d + 3*PLANE_B, pb_l + off);
        asm volatile("cp.async.commit_group;\n");
    }

    for (int kt = 0; kt < 32; ++kt) {
        const int p = kt & 1;
        asm volatile("cp.async.wait_group 1;\n");
        __syncthreads();

        // frag loads
        uint32_t ah[4][4], al[4][4], bh[4][2], bl[4][2];
        #pragma unroll
        for (int mt = 0; mt < 4; ++mt) {
            const int rb = (wm*64 + mt*16 + grp)*STRD + qid;
            ah[mt][0] = sm[p][0][rb];
            ah[mt][1] = sm[p][0][rb + 8*STRD];
            ah[mt][2] = sm[p][0][rb + 4];
            ah[mt][3] = sm[p][0][rb + 8*STRD + 4];
            al[mt][0] = sm[p][1][rb];
            al[mt][1] = sm[p][1][rb + 8*STRD];
            al[mt][2] = sm[p][1][rb + 4];
            al[mt][3] = sm[p][1][rb + 8*STRD + 4];
        }
        #pragma unroll
        for (int nt = 0; nt < 4; ++nt) {
            const int nb = (wn*32 + nt*8 + grp)*STRD + qid;
            bh[nt][0] = sm[p][2][nb];
            bh[nt][1] = sm[p][2][nb + 4];
            bl[nt][0] = sm[p][3][nb];
            bl[nt][1] = sm[p][3][nb + 4];
        }
        #pragma unroll
        for (int mt = 0; mt < 4; ++mt) {
            #pragma unroll
            for (int nt = 0; nt < 4; ++nt) {
                asm volatile(
                    "mma.sync.aligned.m16n8k16.row.col.f32.bf16.bf16.f32 "
                    "{%0,%1,%2,%3}, {%4,%5,%6,%7}, {%8,%9}, {%0,%1,%2,%3};"
                    : "+f"(c[mt][nt][0]), "+f"(c[mt][nt][1]),
                      "+f"(c[mt][nt][2]), "+f"(c[mt][nt][3])
                    : "r"(ah[mt][0]), "r"(ah[mt][1]), "r"(ah[mt][2]), "r"(ah[mt][3]),
                      "r"(bh[nt][0]), "r"(bh[nt][1]));
                asm volatile(
                    "mma.sync.aligned.m16n8k16.row.col.f32.bf16.bf16.f32 "
                    "{%0,%1,%2,%3}, {%4,%5,%6,%7}, {%8,%9}, {%0,%1,%2,%3};"
                    : "+f"(c[mt][nt][0]), "+f"(c[mt][nt][1]),
                      "+f"(c[mt][nt][2]), "+f"(c[mt][nt][3])
                    : "r"(al[mt][0]), "r"(al[mt][1]), "r"(al[mt][2]), "r"(al[mt][3]),
                      "r"(bh[nt][0]), "r"(bh[nt][1]));
                asm volatile(
                    "mma.sync.aligned.m16n8k16.row.col.f32.bf16.bf16.f32 "
                    "{%0,%1,%2,%3}, {%4,%5,%6,%7}, {%8,%9}, {%0,%1,%2,%3};"
                    : "+f"(c[mt][nt][0]), "+f"(c[mt][nt][1]),
                      "+f"(c[mt][nt][2]), "+f"(c[mt][nt][3])
                    : "r"(ah[mt][0]), "r"(ah[mt][1]), "r"(ah[mt][2]), "r"(ah[mt][3]),
                      "r"(bl[nt][0]), "r"(bl[nt][1]));
            }
        }
        __syncthreads();   // everyone done reading stage p
        if (kt + 2 < 32) {
            const int off = (kt+2)*16;
            const uint32_t d = smbase + p*STAGE_B + doff;
            cp16(d + 0*PLANE_B, pa_h + off);
            cp16(d + 1*PLANE_B, pa_l + off);
            cp16(d + 2*PLANE_B, pb_h + off);
            cp16(d + 3*PLANE_B, pb_l + off);
        }
        asm volatile("cp.async.commit_group;\n");
    }

    // epilogue
    #pragma unroll
    for (int mt = 0; mt < 4; ++mt) {
        const int rrow = bm + wm*64 + mt*16 + grp;
        #pragma unroll
        for (int nt = 0; nt < 4; ++nt) {
            const int col = bn + wn*32 + nt*8 + qid*2;
            *(float2*)(Out + (size_t)rrow*CC + col)     = make_float2(c[mt][nt][0], c[mt][nt][1]);
            *(float2*)(Out + (size_t)(rrow+8)*CC + col) = make_float2(c[mt][nt][2], c[mt][nt][3]);
        }
    }
}

// ---------------- WKV6 chunked scan ----------------
// pass1: per (unit, chunk): M = scan from S=0 (no y), P = prod of d
__global__ void wkv_pass1_kernel()
{
    const int gt = blockIdx.x*128 + threadIdx.x;
    const int s = gt & 15;
    const int j = s & 7, p = s >> 3;
    const int i0 = p*4;
    const int ucid = gt >> 4;                    // 0..24575
    const int cch = ucid % NCHUNK;
    const int unit = ucid / NCHUNK;
    const int h = unit & 63, b = (unit >> 6) & 7, dir = unit >> 9;

    const size_t base = (size_t)dir*BTC + (size_t)(b*TT + cch*CLEN)*CC + h*NN;
    const float* kk = g_k + base;
    const float* vv = g_v + base;
    const float* dd = g_d + base;

    float S0=0.f,S1=0.f,S2=0.f,S3=0.f, P0=1.f,P1=1.f,P2=1.f,P3=1.f;
    int off = 0;
    #pragma unroll 4
    for (int t = 0; t < CLEN; ++t, off += CC) {
        const float4 k4 = ld4(kk + off + i0);
        const float4 d4 = ld4(dd + off + i0);
        const float v = vv[off + j];
        S0 = fmaf(d4.x, S0, k4.x*v); P0 *= d4.x;
        S1 = fmaf(d4.y, S1, k4.y*v); P1 *= d4.y;
        S2 = fmaf(d4.z, S2, k4.z*v); P2 *= d4.z;
        S3 = fmaf(d4.w, S3, k4.w*v); P3 *= d4.w;
    }
    float* Mp = g_M + (size_t)ucid*64;
    Mp[(i0+0)*8 + j] = S0;
    Mp[(i0+1)*8 + j] = S1;
    Mp[(i0+2)*8 + j] = S2;
    Mp[(i0+3)*8 + j] = S3;
    if (j == 0) {
        float* Pp = g_P + (size_t)ucid*8;
        Pp[i0+0] = P0; Pp[i0+1] = P1; Pp[i0+2] = P2; Pp[i0+3] = P3;
    }
}

// pass2: sequential stitch over chunks -> initial state per chunk
__global__ void wkv_pass2_kernel()
{
    const int gt = blockIdx.x*128 + threadIdx.x;   // 16384 threads
    const int s = gt & 15;
    const int j = s & 7, p = s >> 3;
    const int i0 = p*4;
    const int unit = gt >> 4;

    float S0=0.f,S1=0.f,S2=0.f,S3=0.f;
    for (int cch = 0; cch < NCHUNK; ++cch) {
        const size_t uc = (size_t)unit*NCHUNK + cch;
        float* Sp = g_S0 + uc*64;
        Sp[(i0+0)*8 + j] = S0;
        Sp[(i0+1)*8 + j] = S1;
        Sp[(i0+2)*8 + j] = S2;
        Sp[(i0+3)*8 + j] = S3;
        const float* Pp = g_P + uc*8;
        const float* Mp = g_M + uc*64;
        S0 = fmaf(Pp[i0+0], S0, Mp[(i0+0)*8 + j]);
        S1 = fmaf(Pp[i0+1], S1, Mp[(i0+1)*8 + j]);
        S2 = fmaf(Pp[i0+2], S2, Mp[(i0+2)*8 + j]);
        S3 = fmaf(Pp[i0+3], S3, Mp[(i0+3)*8 + j]);
    }
}

// pass3: rerun chunks with correct initial state, produce y
__global__ void wkv_pass3_kernel(const float* __restrict__ u)
{
    const int gt = blockIdx.x*128 + threadIdx.x;
    const int s = gt & 15;
    const int j = s & 7, p = s >> 3;
    const int i0 = p*4;
    const int ucid = gt >> 4;
    const int cch = ucid % NCHUNK;
    const int unit = ucid / NCHUNK;
    const int h = unit & 63, b = (unit >> 6) & 7, dir = unit >> 9;

    const float4 uu = ld4(u + h*NN + i0);
    const size_t base = (size_t)dir*BTC + (size_t)(b*TT + cch*CLEN)*CC + h*NN;
    const float* rr = g_r + base;
    const float* kk = g_k + base;
    const float* vv = g_v + base;
    const float* dd = g_d + base;
    float* yy = g_y + base;

    const float* Sp = g_S0 + (size_t)ucid*64;
    float S0 = Sp[(i0+0)*8 + j];
    float S1 = Sp[(i0+1)*8 + j];
    float S2 = Sp[(i0+2)*8 + j];
    float S3 = Sp[(i0+3)*8 + j];

    int off = 0;
    #pragma unroll 2
    for (int t = 0; t < CLEN; ++t, off += CC) {
        const float4 r4 = ld4(rr + off + i0);
        const float4 k4 = ld4(kk + off + i0);
        const float4 d4 = ld4(dd + off + i0);
        const float v = vv[off + j];
        float y = 0.f, kv, tt;
        kv = k4.x*v; tt = fmaf(uu.x, kv, S0); y = fmaf(r4.x, tt, y); S0 = fmaf(d4.x, S0, kv);
        kv = k4.y*v; tt = fmaf(uu.y, kv, S1); y = fmaf(r4.y, tt, y); S1 = fmaf(d4.y, S1, kv);
        kv = k4.z*v; tt = fmaf(uu.z, kv, S2); y = fmaf(r4.z, tt, y); S2 = fmaf(d4.z, S2, kv);
        kv = k4.w*v; tt = fmaf(uu.w, kv, S3); y = fmaf(r4.w, tt, y); S3 = fmaf(d4.w, S3, kv);
        y += __shfl_xor_sync(0xffffffffu, y, 8);
        if (p == 0) yy[off + j] = y;
    }
}

// ---------------- combine directions + layernorm -> bf16 hi/lo planes (slot 6) ----------------
__global__ void combine_ln_kernel(const float* __restrict__ lng,
                                  const float* __restrict__ lnb)
{
    const int t = blockIdx.x, b = blockIdx.y;
    const int tid = threadIdx.x;   // 128
    const int c0 = tid*4;
    const int y = t / HS, xq = t % HS;
    const int tcol = xq*HS + y;
    const int m = b*TT + t;
    const float* yr = g_y + (size_t)m*CC;
    const float* yc = g_y + (size_t)BTC + (size_t)(b*TT + tcol)*CC;

    const float4 va = ld4(yr + c0);
    const float4 vb = ld4(yc + c0);
    float4 o;
    o.x = 0.5f*(va.x + vb.x); o.y = 0.5f*(va.y + vb.y);
    o.z = 0.5f*(va.z + vb.z); o.w = 0.5f*(va.w + vb.w);
    float s  = o.x + o.y + o.z + o.w;
    float sq = o.x*o.x + o.y*o.y + o.z*o.z + o.w*o.w;
    #pragma unroll
    for (int off = 16; off > 0; off >>= 1) {
        s  += __shfl_xor_sync(0xffffffffu, s,  off);
        sq += __shfl_xor_sync(0xffffffffu, sq, off);
    }
    __shared__ float ss[4], sqs[4];
    if ((tid & 31) == 0) { ss[tid >> 5] = s; sqs[tid >> 5] = sq; }
    __syncthreads();
    s  = ss[0] + ss[1] + ss[2] + ss[3];
    sq = sqs[0] + sqs[1] + sqs[2] + sqs[3];
    const float mu = s * (1.0f/CC);
    const float var = sq * (1.0f/CC) - mu*mu;
    const float rstd = rsqrtf(var + 1e-5f);

    const float4 g4 = ld4(lng + c0);
    const float4 b4 = ld4(lnb + c0);
    float4 res;
    res.x = (o.x - mu)*rstd*g4.x + b4.x;
    res.y = (o.y - mu)*rstd*g4.y + b4.y;
    res.z = (o.z - mu)*rstd*g4.z + b4.z;
    res.w = (o.w - mu)*rstd*g4.w + b4.w;
    uint2 hi, lo;
    bfsplit4(res, hi, lo);
    const size_t u2idx = (size_t)m*128 + tid;
    ((uint2*)(g_Ahi + (size_t)6*BTC))[u2idx] = hi;
    ((uint2*)(g_Alo + (size_t)6*BTC))[u2idx] = lo;
}

// ---------------- launch ----------------
extern "C" void kernel_launch(void* const* d_in, const int* in_sizes, int n_in,
                              void* d_out, int out_size)
{
    (void)in_sizes; (void)n_in; (void)out_size;
    const float* x     = (const float*)d_in[0];
    const float* c1    = (const float*)d_in[3];
    const float* c3    = (const float*)d_in[4];
    const float* c5    = (const float*)d_in[5];
    const float* alpha = (const float*)d_in[6];
    const float* maa_w = (const float*)d_in[7];
    const float* maa_k = (const float*)d_in[8];
    const float* maa_v = (const float*)d_in[9];
    const float* maa_r = (const float*)d_in[10];
    const float* tdec  = (const float*)d_in[11];
    const float* w1    = (const float*)d_in[12];
    const float* w2    = (const float*)d_in[13];
    const float* uu    = (const float*)d_in[14];
    const float* Wr    = (const float*)d_in[15];
    const float* Wk    = (const float*)d_in[16];
    const float* Wv    = (const float*)d_in[17];
    const float* Wo    = (const float*)d_in[18];
    const float* lng   = (const float*)d_in[19];
    const float* lnb   = (const float*)d_in[20];

    conv_shift_kernel<<<dim3(HS, BB, 2), 256>>>(x, c1, c3, c5, alpha);
    decay_kernel<<<dim3(TT, BB, 2), 128>>>(x, maa_w, tdec, w1, w2);

    prep_w_kernel<<<(4*CC*CC/4)/256, 256>>>(Wr, Wk, Wv, Wo);
    prep_a_kernel<<<(MM*CC/4)/256, 256>>>(x, maa_r, maa_k, maa_v, 0);
    prep_a_kernel<<<(MM*CC/4)/256, 256>>>(x, maa_r, maa_k, maa_v, 1);

    const dim3 ggrid(CC/128, MM/128);   // (4, 144)
    for (int dir = 0; dir < 2; ++dir) {
        gemm_bf16_kernel<<<ggrid, 256>>>(nullptr, dir*3+0, 0, 0, dir);
        gemm_bf16_kernel<<<ggrid, 256>>>(nullptr, dir*3+1, 1, 1, dir);
        gemm_bf16_kernel<<<ggrid, 256>>>(nullptr, dir*3+2, 2, 2, dir);
    }

    wkv_pass1_kernel<<<(NUNIT*NCHUNK*16)/128, 128>>>();
    wkv_pass2_kernel<<<(NUNIT*16)/128, 128>>>();
    wkv_pass3_kernel<<<(NUNIT*NCHUNK*16)/128, 128>>>(uu);

    combine_ln_kernel<<<dim3(TT, BB), 128>>>(lng, lnb);
    gemm_bf16_kernel<<<ggrid, 256>>>((float*)d_out, 6, 3, 3, 0);
}

// round 5
// speedup vs baseline: 2.6303x; 1.0993x over previous
#include <cuda_runtime.h>
#include <cuda_bf16.h>
#include <cstdint>

#define BB 8
#define TT 2304
#define CC 512
#define HS 48
#define HH 64
#define NN 8
#define MM (BB*TT)
#define BTC (MM*CC)
#define NCHUNK 24
#define CLEN 96          // TT / NCHUNK
#define NUNIT 1024       // 2 * BB * HH

// ---------------- scratch (device globals) ----------------
__device__ float g_xx[2*BTC];
__device__ float g_r [2*BTC];
__device__ float g_k [2*BTC];
__device__ float g_v [2*BTC];
__device__ float g_d [2*BTC];
__device__ float g_y [2*BTC];
// bf16 hi/lo planes: A variants 0..5 = dir*3 + {r,k,v}; 6 = layernormed
__device__ uint16_t g_Ahi[7*(size_t)BTC];
__device__ uint16_t g_Alo[7*(size_t)BTC];
__device__ uint16_t g_Whi[4*CC*CC];   // 0=Wr 1=Wk 2=Wv 3=Wo
__device__ uint16_t g_Wlo[4*CC*CC];
// chunked scan scratch
__device__ float g_M [NUNIT*NCHUNK*64];
__device__ float g_P [NUNIT*NCHUNK*8];
__device__ float g_S0[NUNIT*NCHUNK*64];

__device__ __forceinline__ float4 ld4(const float* p) { return *(const float4*)p; }

__device__ __forceinline__ void bfsplit4(float4 v, uint2& hi, uint2& lo) {
    __nv_bfloat16 hx = __float2bfloat16(v.x);
    __nv_bfloat16 hy = __float2bfloat16(v.y);
    __nv_bfloat16 hz = __float2bfloat16(v.z);
    __nv_bfloat16 hw = __float2bfloat16(v.w);
    float rx = v.x - __bfloat162float(hx);
    float ry = v.y - __bfloat162float(hy);
    float rz = v.z - __bfloat162float(hz);
    float rw = v.w - __bfloat162float(hw);
    __nv_bfloat16 lx = __float2bfloat16(rx);
    __nv_bfloat16 ly = __float2bfloat16(ry);
    __nv_bfloat16 lz = __float2bfloat16(rz);
    __nv_bfloat16 lw = __float2bfloat16(rw);
    hi.x = ((uint32_t)__bfloat16_as_ushort(hy) << 16) | __bfloat16_as_ushort(hx);
    hi.y = ((uint32_t)__bfloat16_as_ushort(hw) << 16) | __bfloat16_as_ushort(hz);
    lo.x = ((uint32_t)__bfloat16_as_ushort(ly) << 16) | __bfloat16_as_ushort(lx);
    lo.y = ((uint32_t)__bfloat16_as_ushort(lw) << 16) | __bfloat16_as_ushort(lz);
}

// ---------------- conv shift ----------------
__global__ void conv_shift_kernel(const float* __restrict__ x,
                                  const float* __restrict__ c1,
                                  const float* __restrict__ c3,
                                  const float* __restrict__ c5,
                                  const float* __restrict__ alpha)
{
    const int u   = blockIdx.x;
    const int b   = blockIdx.y;
    const int dir = blockIdx.z;
    const int lc  = threadIdx.x & 127;
    const int qh  = threadIdx.x >> 7;
    const float a0 = alpha[0], a1 = alpha[1], a2 = alpha[2], a3 = alpha[3];
    const float* xb = x + (size_t)b*TT*CC;
    float* xxb = g_xx + (size_t)dir*BTC + (size_t)b*TT*CC;

    for (int c0 = 0; c0 < CC; c0 += 128) {
        const int c = c0 + lc;
        float coef[5][5];
        #pragma unroll
        for (int i = 0; i < 5; ++i) {
            #pragma unroll
            for (int j = 0; j < 5; ++j) {
                float w = a3 * c5[c*25 + i*5 + j];
                if (i >= 1 && i <= 3 && j >= 1 && j <= 3)
                    w += a2 * c3[c*9 + (i-1)*3 + (j-1)];
                if (i == 2 && j == 2)
                    w += a1 * c1[c] + a0 - 1.0f;
                coef[i][j] = w;
            }
        }
        for (int q = qh; q < HS; q += 2) {
            float acc = 0.0f;
            #pragma unroll
            for (int i = 0; i < 5; ++i) {
                const int uu = u + i - 2;
                if (uu < 0 || uu >= HS) continue;
                #pragma unroll
                for (int j = 0; j < 5; ++j) {
                    const int qq = q + j - 2;
                    if (qq < 0 || qq >= HS) continue;
                    const int idx = dir ? (qq*HS + uu) : (uu*HS + qq);
                    acc = fmaf(coef[i][j], xb[(size_t)idx*CC + c], acc);
                }
            }
            xxb[(size_t)(u*HS + q)*CC + c] = acc;
        }
    }
}

// ---------------- decay ----------------
__global__ void decay_kernel(const float* __restrict__ x,
                             const float* __restrict__ maa_w,
                             const float* __restrict__ tdec,
                             const float* __restrict__ w1,
                             const float* __restrict__ w2)
{
    const int t = blockIdx.x, b = blockIdx.y, dir = blockIdx.z;
    const int m = b*TT + t;
    const int row = dir ? (b*TT + (t % HS)*HS + (t / HS)) : m;
    const int tid = threadIdx.x;   // 128
    float p[16];
    #pragma unroll
    for (int j = 0; j < 16; ++j) p[j] = 0.0f;
    #pragma unroll
    for (int i = 0; i < 4; ++i) {
        const int c = tid + i*128;
        const float v = x[(size_t)row*CC + c]
                      + g_xx[(size_t)dir*BTC + (size_t)m*CC + c] * maa_w[c];
        const float4* wr4 = (const float4*)(w1 + c*16);
        const float4 wa = wr4[0], wb = wr4[1], wc = wr4[2], wd = wr4[3];
        p[0]  = fmaf(v, wa.x, p[0]);  p[1]  = fmaf(v, wa.y, p[1]);
        p[2]  = fmaf(v, wa.z, p[2]);  p[3]  = fmaf(v, wa.w, p[3]);
        p[4]  = fmaf(v, wb.x, p[4]);  p[5]  = fmaf(v, wb.y, p[5]);
        p[6]  = fmaf(v, wb.z, p[6]);  p[7]  = fmaf(v, wb.w, p[7]);
        p[8]  = fmaf(v, wc.x, p[8]);  p[9]  = fmaf(v, wc.y, p[9]);
        p[10] = fmaf(v, wc.z, p[10]); p[11] = fmaf(v, wc.w, p[11]);
        p[12] = fmaf(v, wd.x, p[12]); p[13] = fmaf(v, wd.y, p[13]);
        p[14] = fmaf(v, wd.z, p[14]); p[15] = fmaf(v, wd.w, p[15]);
    }
    #pragma unroll
    for (int j = 0; j < 16; ++j) {
        #pragma unroll
        for (int off = 16; off > 0; off >>= 1)
            p[j] += __shfl_xor_sync(0xffffffffu, p[j], off);
    }
    __shared__ float ps[4][16];
    __shared__ float th[16];
    if ((tid & 31) == 0) {
        #pragma unroll
        for (int j = 0; j < 16; ++j) ps[tid >> 5][j] = p[j];
    }
    __syncthreads();
    if (tid < 16) th[tid] = tanhf(ps[0][tid] + ps[1][tid] + ps[2][tid] + ps[3][tid]);
    __syncthreads();
    #pragma unroll
    for (int i = 0; i < 4; ++i) {
        const int c = tid + i*128;
        float wv = tdec[c];
        #pragma unroll
        for (int j = 0; j < 16; ++j) wv = fmaf(th[j], w2[j*CC + c], wv);
        g_d[(size_t)dir*BTC + (size_t)m*CC + c] = expf(-expf(wv));
    }
}

// ---------------- prep: W -> bf16 hi/lo planes (8 ch/thread) ----------------
__global__ void prep_w_kernel(const float* __restrict__ Wr, const float* __restrict__ Wk,
                              const float* __restrict__ Wv, const float* __restrict__ Wo)
{
    const int idx = blockIdx.x*256 + threadIdx.x;       // over 4*CC*CC/8
    const int w = idx >> 15;                             // CC*CC/8 = 32768
    const int r = idx & 32767;
    const float* W = (w==0) ? Wr : (w==1) ? Wk : (w==2) ? Wv : Wo;
    const float4 va = ld4(W + (size_t)r*8);
    const float4 vb = ld4(W + (size_t)r*8 + 4);
    uint2 ha, la, hb, lb;
    bfsplit4(va, ha, la);
    bfsplit4(vb, hb, lb);
    ((uint4*)(g_Whi + (size_t)w*CC*CC))[r] = make_uint4(ha.x, ha.y, hb.x, hb.y);
    ((uint4*)(g_Wlo + (size_t)w*CC*CC))[r] = make_uint4(la.x, la.y, lb.x, lb.y);
}

// ---------------- prep: A variants (x[perm] + xx*maa) -> bf16 hi/lo planes ----------------
__global__ void prep_a_kernel(const float* __restrict__ x,
                              const float* __restrict__ maar,
                              const float* __restrict__ maak,
                              const float* __restrict__ maav,
                              int dir)
{
    const int idx = blockIdx.x*256 + threadIdx.x;       // over MM*CC/8
    const int m  = idx >> 6;
    const int c8 = (idx & 63) * 8;
    int xr;
    if (dir) { const int t = m % TT, bq = m / TT; xr = bq*TT + (t % HS)*HS + (t / HS); }
    else xr = m;
    const float4 xva  = ld4(x + (size_t)xr*CC + c8);
    const float4 xvb  = ld4(x + (size_t)xr*CC + c8 + 4);
    const float4 xxa = ld4(g_xx + (size_t)dir*BTC + (size_t)m*CC + c8);
    const float4 xxb = ld4(g_xx + (size_t)dir*BTC + (size_t)m*CC + c8 + 4);
    const float* maas[3] = {maar, maak, maav};
    #pragma unroll
    for (int v = 0; v < 3; ++v) {
        const float4 ma = ld4(maas[v] + c8);
        const float4 mb = ld4(maas[v] + c8 + 4);
        float4 a, b;
        a.x = fmaf(xxa.x, ma.x, xva.x); a.y = fmaf(xxa.y, ma.y, xva.y);
        a.z = fmaf(xxa.z, ma.z, xva.z); a.w = fmaf(xxa.w, ma.w, xva.w);
        b.x = fmaf(xxb.x, mb.x, xvb.x); b.y = fmaf(xxb.y, mb.y, xvb.y);
        b.z = fmaf(xxb.z, mb.z, xvb.z); b.w = fmaf(xxb.w, mb.w, xvb.w);
        uint2 ha, la, hb, lb;
        bfsplit4(a, ha, la);
        bfsplit4(b, hb, lb);
        const size_t vb = (size_t)(dir*3 + v) * BTC;
        ((uint4*)(g_Ahi + vb))[idx] = make_uint4(ha.x, ha.y, hb.x, hb.y);
        ((uint4*)(g_Alo + vb))[idx] = make_uint4(la.x, la.y, lb.x, lb.y);
    }
}

// ---------------- bf16-split tensor-core GEMM: Out[m][n] = sum_k A[m][k]*W[n][k] ----------------
// 3-stage cp.async pipeline, XOR-swizzled smem (8 u32/row), ldmatrix frag loads.
#define BKW 8                       // u32 per row per plane (16 bf16)
#define PLANE_W (128*BKW)           // 1024 u32
#define PLANE_B (PLANE_W*4)         // 4096 B
#define STAGE_B (PLANE_B*4)         // 16384 B

__device__ __forceinline__ void cp16(uint32_t dst, const void* src) {
    asm volatile("cp.async.cg.shared.global [%0], [%1], 16;\n" :: "r"(dst), "l"(src));
}
__device__ __forceinline__ void ldsm4(uint32_t* r, uint32_t a) {
    asm volatile("ldmatrix.sync.aligned.m8n8.x4.shared.b16 {%0,%1,%2,%3}, [%4];"
        : "=r"(r[0]), "=r"(r[1]), "=r"(r[2]), "=r"(r[3]) : "r"(a));
}
__device__ __forceinline__ void ldsm2(uint32_t* r, uint32_t a) {
    asm volatile("ldmatrix.sync.aligned.m8n8.x2.shared.b16 {%0,%1}, [%2];"
        : "=r"(r[0]), "=r"(r[1]) : "r"(a));
}

__global__ __launch_bounds__(256)
void gemm_bf16_kernel(float* __restrict__ Out_ext, int a_sel, int w_sel, int out_sel, int dir)
{
    __shared__ uint32_t sm[3][4][PLANE_W];   // [stage][Ahi,Alo,Bhi,Blo] = 48KB

    const int tid = threadIdx.x;
    const int bn = blockIdx.x * 128;
    const int bm = blockIdx.y * 128;

    const uint16_t* Ah = g_Ahi + (size_t)a_sel*BTC;
    const uint16_t* Al = g_Alo + (size_t)a_sel*BTC;
    const uint16_t* Bh = g_Whi + (size_t)w_sel*CC*CC;
    const uint16_t* Bl = g_Wlo + (size_t)w_sel*CC*CC;
    float* Out;
    switch (out_sel) {
        case 0: Out = g_r + (size_t)dir*BTC; break;
        case 1: Out = g_k + (size_t)dir*BTC; break;
        case 2: Out = g_v + (size_t)dir*BTC; break;
        default: Out = Out_ext; break;
    }

    // ---- staging: one 16B chunk per plane per thread per ktile ----
    const int row  = tid >> 1;
    const int half = tid & 1;
    const int halfsw = half ^ ((row >> 2) & 1);         // XOR swizzle
    const uint16_t* pa_h = Ah + (size_t)(bm + row)*CC + half*8;
    const uint16_t* pa_l = Al + (size_t)(bm + row)*CC + half*8;
    const uint16_t* pb_h = Bh + (size_t)(bn + row)*CC + half*8;
    const uint16_t* pb_l = Bl + (size_t)(bn + row)*CC + half*8;
    const uint32_t smbase = (uint32_t)__cvta_generic_to_shared(&sm[0][0][0]);
    const uint32_t doff = (uint32_t)(row*32 + halfsw*16);

    const int lane = tid & 31;
    const int grp  = lane >> 2;
    const int qid  = lane & 3;
    const int wid  = tid >> 5;
    const int wm   = wid >> 2;
    const int wn   = wid & 3;

    // ldmatrix lane offsets (bytes within plane)
    const int selA = lane >> 3;                              // 0..3
    const int rA   = wm*64 + ((selA & 1) << 3) + (lane & 7); // + mt*16 later
    const int hA   = (selA >> 1) ^ ((rA >> 2) & 1);
    const uint32_t offA = (uint32_t)(rA*32 + hA*16);
    const int l15  = lane & 15;
    const int selB = l15 >> 3;                               // 0..1
    const int rB   = wn*32 + (l15 & 7);                      // + nt*8 later
    const int hB   = selB ^ ((rB >> 2) & 1);
    const uint32_t offB = (uint32_t)(rB*32 + hB*16);

    float c[4][4][4];
    #pragma unroll
    for (int mt = 0; mt < 4; ++mt)
        #pragma unroll
        for (int nt = 0; nt < 4; ++nt)
            #pragma unroll
            for (int e = 0; e < 4; ++e) c[mt][nt][e] = 0.0f;

    // prologue: prefetch ktiles 0,1 into stages 0,1
    #pragma unroll
    for (int kt = 0; kt < 2; ++kt) {
        const uint32_t d = smbase + kt*STAGE_B + doff;
        const int off = kt*16;
        cp16(d + 0*PLANE_B, pa_h + off);
        cp16(d + 1*PLANE_B, pa_l + off);
        cp16(d + 2*PLANE_B, pb_h + off);
        cp16(d + 3*PLANE_B, pb_l + off);
        asm volatile("cp.async.commit_group;\n");
    }

    int p = 0;
    for (int kt = 0; kt < 32; ++kt) {
        asm volatile("cp.async.wait_group 1;\n");
        __syncthreads();

        const uint32_t sb = smbase + p*STAGE_B;
        uint32_t ah[4][4], al[4][4], bh[4][2], bl[4][2];
        #pragma unroll
        for (int mt = 0; mt < 4; ++mt) ldsm4(ah[mt], sb + 0*PLANE_B + mt*512 + offA);
        #pragma unroll
        for (int mt = 0; mt < 4; ++mt) ldsm4(al[mt], sb + 1*PLANE_B + mt*512 + offA);
        #pragma unroll
        for (int nt = 0; nt < 4; ++nt) ldsm2(bh[nt], sb + 2*PLANE_B + nt*256 + offB);
        #pragma unroll
        for (int nt = 0; nt < 4; ++nt) ldsm2(bl[nt], sb + 3*PLANE_B + nt*256 + offB);

        #pragma unroll
        for (int mt = 0; mt < 4; ++mt) {
            #pragma unroll
            for (int nt = 0; nt < 4; ++nt) {
                asm volatile(
                    "mma.sync.aligned.m16n8k16.row.col.f32.bf16.bf16.f32 "
                    "{%0,%1,%2,%3}, {%4,%5,%6,%7}, {%8,%9}, {%0,%1,%2,%3};"
                    : "+f"(c[mt][nt][0]), "+f"(c[mt][nt][1]),
                      "+f"(c[mt][nt][2]), "+f"(c[mt][nt][3])
                    : "r"(ah[mt][0]), "r"(ah[mt][1]), "r"(ah[mt][2]), "r"(ah[mt][3]),
                      "r"(bh[nt][0]), "r"(bh[nt][1]));
                asm volatile(
                    "mma.sync.aligned.m16n8k16.row.col.f32.bf16.bf16.f32 "
                    "{%0,%1,%2,%3}, {%4,%5,%6,%7}, {%8,%9}, {%0,%1,%2,%3};"
                    : "+f"(c[mt][nt][0]), "+f"(c[mt][nt][1]),
                      "+f"(c[mt][nt][2]), "+f"(c[mt][nt][3])
                    : "r"(al[mt][0]), "r"(al[mt][1]), "r"(al[mt][2]), "r"(al[mt][3]),
                      "r"(bh[nt][0]), "r"(bh[nt][1]));
                asm volatile(
                    "mma.sync.aligned.m16n8k16.row.col.f32.bf16.bf16.f32 "
                    "{%0,%1,%2,%3}, {%4,%5,%6,%7}, {%8,%9}, {%0,%1,%2,%3};"
                    : "+f"(c[mt][nt][0]), "+f"(c[mt][nt][1]),
                      "+f"(c[mt][nt][2]), "+f"(c[mt][nt][3])
                    : "r"(ah[mt][0]), "r"(ah[mt][1]), "r"(ah[mt][2]), "r"(ah[mt][3]),
                      "r"(bl[nt][0]), "r"(bl[nt][1]));
            }
        }

        // prefetch ktile kt+2 into the stage consumed at iteration kt-1
        if (kt < 30) {
            int ps = p + 2; if (ps >= 3) ps -= 3;
            const uint32_t d = smbase + ps*STAGE_B + doff;
            const int off = (kt+2)*16;
            cp16(d + 0*PLANE_B, pa_h + off);
            cp16(d + 1*PLANE_B, pa_l + off);
            cp16(d + 2*PLANE_B, pb_h + off);
            cp16(d + 3*PLANE_B, pb_l + off);
        }
        asm volatile("cp.async.commit_group;\n");
        if (++p == 3) p = 0;
    }

    // epilogue
    #pragma unroll
    for (int mt = 0; mt < 4; ++mt) {
        const int rrow = bm + wm*64 + mt*16 + grp;
        #pragma unroll
        for (int nt = 0; nt < 4; ++nt) {
            const int col = bn + wn*32 + nt*8 + qid*2;
            *(float2*)(Out + (size_t)rrow*CC + col)     = make_float2(c[mt][nt][0], c[mt][nt][1]);
            *(float2*)(Out + (size_t)(rrow+8)*CC + col) = make_float2(c[mt][nt][2], c[mt][nt][3]);
        }
    }
}

// ---------------- WKV6 chunked scan ----------------
__global__ void wkv_pass1_kernel()
{
    const int gt = blockIdx.x*128 + threadIdx.x;
    const int s = gt & 15;
    const int j = s & 7, p = s >> 3;
    const int i0 = p*4;
    const int ucid = gt >> 4;
    const int cch = ucid % NCHUNK;
    const int unit = ucid / NCHUNK;
    const int h = unit & 63, b = (unit >> 6) & 7, dir = unit >> 9;

    const size_t base = (size_t)dir*BTC + (size_t)(b*TT + cch*CLEN)*CC + h*NN;
    const float* kk = g_k + base;
    const float* vv = g_v + base;
    const float* dd = g_d + base;

    float S0=0.f,S1=0.f,S2=0.f,S3=0.f, P0=1.f,P1=1.f,P2=1.f,P3=1.f;
    int off = 0;
    #pragma unroll 4
    for (int t = 0; t < CLEN; ++t, off += CC) {
        const float4 k4 = ld4(kk + off + i0);
        const float4 d4 = ld4(dd + off + i0);
        const float v = vv[off + j];
        S0 = fmaf(d4.x, S0, k4.x*v); P0 *= d4.x;
        S1 = fmaf(d4.y, S1, k4.y*v); P1 *= d4.y;
        S2 = fmaf(d4.z, S2, k4.z*v); P2 *= d4.z;
        S3 = fmaf(d4.w, S3, k4.w*v); P3 *= d4.w;
    }
    float* Mp = g_M + (size_t)ucid*64;
    Mp[(i0+0)*8 + j] = S0;
    Mp[(i0+1)*8 + j] = S1;
    Mp[(i0+2)*8 + j] = S2;
    Mp[(i0+3)*8 + j] = S3;
    if (j == 0) {
        float* Pp = g_P + (size_t)ucid*8;
        Pp[i0+0] = P0; Pp[i0+1] = P1; Pp[i0+2] = P2; Pp[i0+3] = P3;
    }
}

__global__ void wkv_pass2_kernel()
{
    const int gt = blockIdx.x*128 + threadIdx.x;   // 16384 threads
    const int s = gt & 15;
    const int j = s & 7, p = s >> 3;
    const int i0 = p*4;
    const int unit = gt >> 4;

    float S0=0.f,S1=0.f,S2=0.f,S3=0.f;
    for (int cch = 0; cch < NCHUNK; ++cch) {
        const size_t uc = (size_t)unit*NCHUNK + cch;
        float* Sp = g_S0 + uc*64;
        Sp[(i0+0)*8 + j] = S0;
        Sp[(i0+1)*8 + j] = S1;
        Sp[(i0+2)*8 + j] = S2;
        Sp[(i0+3)*8 + j] = S3;
        const float* Pp = g_P + uc*8;
        const float* Mp = g_M + uc*64;
        S0 = fmaf(Pp[i0+0], S0, Mp[(i0+0)*8 + j]);
        S1 = fmaf(Pp[i0+1], S1, Mp[(i0+1)*8 + j]);
        S2 = fmaf(Pp[i0+2], S2, Mp[(i0+2)*8 + j]);
        S3 = fmaf(Pp[i0+3], S3, Mp[(i0+3)*8 + j]);
    }
}

__global__ void wkv_pass3_kernel(const float* __restrict__ u)
{
    const int gt = blockIdx.x*128 + threadIdx.x;
    const int s = gt & 15;
    const int j = s & 7, p = s >> 3;
    const int i0 = p*4;
    const int ucid = gt >> 4;
    const int cch = ucid % NCHUNK;
    const int unit = ucid / NCHUNK;
    const int h = unit & 63, b = (unit >> 6) & 7, dir = unit >> 9;

    const float4 uu = ld4(u + h*NN + i0);
    const size_t base = (size_t)dir*BTC + (size_t)(b*TT + cch*CLEN)*CC + h*NN;
    const float* rr = g_r + base;
    const float* kk = g_k + base;
    const float* vv = g_v + base;
    const float* dd = g_d + base;
    float* yy = g_y + base;

    const float* Sp = g_S0 + (size_t)ucid*64;
    float S0 = Sp[(i0+0)*8 + j];
    float S1 = Sp[(i0+1)*8 + j];
    float S2 = Sp[(i0+2)*8 + j];
    float S3 = Sp[(i0+3)*8 + j];

    int off = 0;
    #pragma unroll 2
    for (int t = 0; t < CLEN; ++t, off += CC) {
        const float4 r4 = ld4(rr + off + i0);
        const float4 k4 = ld4(kk + off + i0);
        const float4 d4 = ld4(dd + off + i0);
        const float v = vv[off + j];
        float y = 0.f, kv, tt;
        kv = k4.x*v; tt = fmaf(uu.x, kv, S0); y = fmaf(r4.x, tt, y); S0 = fmaf(d4.x, S0, kv);
        kv = k4.y*v; tt = fmaf(uu.y, kv, S1); y = fmaf(r4.y, tt, y); S1 = fmaf(d4.y, S1, kv);
        kv = k4.z*v; tt = fmaf(uu.z, kv, S2); y = fmaf(r4.z, tt, y); S2 = fmaf(d4.z, S2, kv);
        kv = k4.w*v; tt = fmaf(uu.w, kv, S3); y = fmaf(r4.w, tt, y); S3 = fmaf(d4.w, S3, kv);
        y += __shfl_xor_sync(0xffffffffu, y, 8);
        if (p == 0) yy[off + j] = y;
    }
}

// ---------------- combine directions + layernorm -> bf16 hi/lo planes (slot 6) ----------------
__global__ void combine_ln_kernel(const float* __restrict__ lng,
                                  const float* __restrict__ lnb)
{
    const int t = blockIdx.x, b = blockIdx.y;
    const int tid = threadIdx.x;   // 128
    const int c0 = tid*4;
    const int y = t / HS, xq = t % HS;
    const int tcol = xq*HS + y;
    const int m = b*TT + t;
    const float* yr = g_y + (size_t)m*CC;
    const float* yc = g_y + (size_t)BTC + (size_t)(b*TT + tcol)*CC;

    const float4 va = ld4(yr + c0);
    const float4 vb = ld4(yc + c0);
    float4 o;
    o.x = 0.5f*(va.x + vb.x); o.y = 0.5f*(va.y + vb.y);
    o.z = 0.5f*(va.z + vb.z); o.w = 0.5f*(va.w + vb.w);
    float s  = o.x + o.y + o.z + o.w;
    float sq = o.x*o.x + o.y*o.y + o.z*o.z + o.w*o.w;
    #pragma unroll
    for (int off = 16; off > 0; off >>= 1) {
        s  += __shfl_xor_sync(0xffffffffu, s,  off);
        sq += __shfl_xor_sync(0xffffffffu, sq, off);
    }
    __shared__ float ss[4], sqs[4];
    if ((tid & 31) == 0) { ss[tid >> 5] = s; sqs[tid >> 5] = sq; }
    __syncthreads();
    s  = ss[0] + ss[1] + ss[2] + ss[3];
    sq = sqs[0] + sqs[1] + sqs[2] + sqs[3];
    const float mu = s * (1.0f/CC);
    const float var = sq * (1.0f/CC) - mu*mu;
    const float rstd = rsqrtf(var + 1e-5f);

    const float4 g4 = ld4(lng + c0);
    const float4 b4 = ld4(lnb + c0);
    float4 res;
    res.x = (o.x - mu)*rstd*g4.x + b4.x;
    res.y = (o.y - mu)*rstd*g4.y + b4.y;
    res.z = (o.z - mu)*rstd*g4.z + b4.z;
    res.w = (o.w - mu)*rstd*g4.w + b4.w;
    uint2 hi, lo;
    bfsplit4(res, hi, lo);
    const size_t u2idx = (size_t)m*128 + tid;
    ((uint2*)(g_Ahi + (size_t)6*BTC))[u2idx] = hi;
    ((uint2*)(g_Alo + (size_t)6*BTC))[u2idx] = lo;
}

// ---------------- launch ----------------
extern "C" void kernel_launch(void* const* d_in, const int* in_sizes, int n_in,
                              void* d_out, int out_size)
{
    (void)in_sizes; (void)n_in; (void)out_size;
    const float* x     = (const float*)d_in[0];
    const float* c1    = (const float*)d_in[3];
    const float* c3    = (const float*)d_in[4];
    const float* c5    = (const float*)d_in[5];
    const float* alpha = (const float*)d_in[6];
    const float* maa_w = (const float*)d_in[7];
    const float* maa_k = (const float*)d_in[8];
    const float* maa_v = (const float*)d_in[9];
    const float* maa_r = (const float*)d_in[10];
    const float* tdec  = (const float*)d_in[11];
    const float* w1    = (const float*)d_in[12];
    const float* w2    = (const float*)d_in[13];
    const float* uu    = (const float*)d_in[14];
    const float* Wr    = (const float*)d_in[15];
    const float* Wk    = (const float*)d_in[16];
    const float* Wv    = (const float*)d_in[17];
    const float* Wo    = (const float*)d_in[18];
    const float* lng   = (const float*)d_in[19];
    const float* lnb   = (const float*)d_in[20];

    conv_shift_kernel<<<dim3(HS, BB, 2), 256>>>(x, c1, c3, c5, alpha);
    decay_kernel<<<dim3(TT, BB, 2), 128>>>(x, maa_w, tdec, w1, w2);

    prep_w_kernel<<<(4*CC*CC/8)/256, 256>>>(Wr, Wk, Wv, Wo);
    prep_a_kernel<<<(MM*CC/8)/256, 256>>>(x, maa_r, maa_k, maa_v, 0);
    prep_a_kernel<<<(MM*CC/8)/256, 256>>>(x, maa_r, maa_k, maa_v, 1);

    const dim3 ggrid(CC/128, MM/128);   // (4, 144)
    for (int dir = 0; dir < 2; ++dir) {
        gemm_bf16_kernel<<<ggrid, 256>>>(nullptr, dir*3+0, 0, 0, dir);
        gemm_bf16_kernel<<<ggrid, 256>>>(nullptr, dir*3+1, 1, 1, dir);
        gemm_bf16_kernel<<<ggrid, 256>>>(nullptr, dir*3+2, 2, 2, dir);
    }

    wkv_pass1_kernel<<<(NUNIT*NCHUNK*16)/128, 128>>>();
    wkv_pass2_kernel<<<(NUNIT*16)/128, 128>>>();
    wkv_pass3_kernel<<<(NUNIT*NCHUNK*16)/128, 128>>>(uu);

    combine_ln_kernel<<<dim3(TT, BB), 128>>>(lng, lnb);
    gemm_bf16_kernel<<<ggrid, 256>>>((float*)d_out, 6, 3, 3, 0);
}

// round 6
// speedup vs baseline: 2.8774x; 1.0939x over previous
#include <cuda_runtime.h>
#include <cuda_bf16.h>
#include <cstdint>

#define BB 8
#define TT 2304
#define CC 512
#define HS 48
#define HH 64
#define NN 8
#define MM (BB*TT)
#define BTC (MM*CC)
#define NCHUNK 24
#define CLEN 96          // TT / NCHUNK
#define NUNIT 1024       // 2 * BB * HH

// ---------------- scratch (device globals) ----------------
__device__ float g_xx[2*BTC];
__device__ float g_r [2*BTC];
__device__ float g_k [2*BTC];
__device__ float g_v [2*BTC];
__device__ float g_d [2*BTC];
__device__ float g_y [2*BTC];
__device__ float g_coef[25*CC];      // merged 5x5 stencil per channel, [tap][c]
// bf16 hi/lo planes: A variants 0..5 = dir*3 + {r,k,v}; 6 = layernormed
__device__ uint16_t g_Ahi[7*(size_t)BTC];
__device__ uint16_t g_Alo[7*(size_t)BTC];
__device__ uint16_t g_Whi[4*CC*CC];   // 0=Wr 1=Wk 2=Wv 3=Wo
__device__ uint16_t g_Wlo[4*CC*CC];
// chunked scan scratch
__device__ float g_M [NUNIT*NCHUNK*64];
__device__ float g_P [NUNIT*NCHUNK*8];
__device__ float g_S0[NUNIT*NCHUNK*64];

__device__ __forceinline__ float4 ld4(const float* p) { return *(const float4*)p; }

__device__ __forceinline__ void bfsplit4(float4 v, uint2& hi, uint2& lo) {
    __nv_bfloat16 hx = __float2bfloat16(v.x);
    __nv_bfloat16 hy = __float2bfloat16(v.y);
    __nv_bfloat16 hz = __float2bfloat16(v.z);
    __nv_bfloat16 hw = __float2bfloat16(v.w);
    float rx = v.x - __bfloat162float(hx);
    float ry = v.y - __bfloat162float(hy);
    float rz = v.z - __bfloat162float(hz);
    float rw = v.w - __bfloat162float(hw);
    __nv_bfloat16 lx = __float2bfloat16(rx);
    __nv_bfloat16 ly = __float2bfloat16(ry);
    __nv_bfloat16 lz = __float2bfloat16(rz);
    __nv_bfloat16 lw = __float2bfloat16(rw);
    hi.x = ((uint32_t)__bfloat16_as_ushort(hy) << 16) | __bfloat16_as_ushort(hx);
    hi.y = ((uint32_t)__bfloat16_as_ushort(hw) << 16) | __bfloat16_as_ushort(hz);
    lo.x = ((uint32_t)__bfloat16_as_ushort(ly) << 16) | __bfloat16_as_ushort(lx);
    lo.y = ((uint32_t)__bfloat16_as_ushort(lw) << 16) | __bfloat16_as_ushort(lz);
}

// ---------------- merged stencil coefficients ----------------
__global__ void prep_coef_kernel(const float* __restrict__ c1,
                                 const float* __restrict__ c3,
                                 const float* __restrict__ c5,
                                 const float* __restrict__ alpha)
{
    const int c = threadIdx.x;   // 512
    const float a0 = alpha[0], a1 = alpha[1], a2 = alpha[2], a3 = alpha[3];
    #pragma unroll
    for (int i = 0; i < 5; ++i) {
        #pragma unroll
        for (int j = 0; j < 5; ++j) {
            float w = a3 * c5[c*25 + i*5 + j];
            if (i >= 1 && i <= 3 && j >= 1 && j <= 3)
                w += a2 * c3[c*9 + (i-1)*3 + (j-1)];
            if (i == 2 && j == 2)
                w += a1 * c1[c] + a0 - 1.0f;    // -1: xx = sh - x
            g_coef[(i*5+j)*CC + c] = w;
        }
    }
}

// ---------------- conv shift (float4 channels) ----------------
__global__ void conv_shift_kernel(const float* __restrict__ x)
{
    const int u   = blockIdx.x;
    const int b   = blockIdx.y;
    const int dir = blockIdx.z;
    const int c0  = (threadIdx.x & 127) * 4;     // 4 channels per thread
    const int qh  = threadIdx.x >> 7;
    const float* xb = x + (size_t)b*TT*CC;
    float* xxb = g_xx + (size_t)dir*BTC + (size_t)b*TT*CC;

    for (int q = qh; q < HS; q += 2) {
        float4 acc = make_float4(0.f, 0.f, 0.f, 0.f);
        #pragma unroll
        for (int i = 0; i < 5; ++i) {
            const int uu = u + i - 2;
            if (uu < 0 || uu >= HS) continue;
            #pragma unroll
            for (int j = 0; j < 5; ++j) {
                const int qq = q + j - 2;
                if (qq < 0 || qq >= HS) continue;
                const int idx = dir ? (qq*HS + uu) : (uu*HS + qq);
                const float4 cf = ld4(g_coef + (i*5+j)*CC + c0);
                const float4 xv = ld4(xb + (size_t)idx*CC + c0);
                acc.x = fmaf(cf.x, xv.x, acc.x);
                acc.y = fmaf(cf.y, xv.y, acc.y);
                acc.z = fmaf(cf.z, xv.z, acc.z);
                acc.w = fmaf(cf.w, xv.w, acc.w);
            }
        }
        *(float4*)(xxb + (size_t)(u*HS + q)*CC + c0) = acc;
    }
}

// ---------------- fused decay + bf16 plane prep ----------------
// One read of x[perm] + xx per (dir, position): writes g_d and the 3 A-variant planes.
__global__ void fused_dp_kernel(const float* __restrict__ x,
                                const float* __restrict__ maa_w,
                                const float* __restrict__ maar,
                                const float* __restrict__ maak,
                                const float* __restrict__ maav,
                                const float* __restrict__ tdec,
                                const float* __restrict__ w1,   // [C][16]
                                const float* __restrict__ w2)   // [16][C]
{
    const int t = blockIdx.x, b = blockIdx.y, dir = blockIdx.z;
    const int m = b*TT + t;
    const int row = dir ? (b*TT + (t % HS)*HS + (t / HS)) : m;
    const int tid = threadIdx.x;   // 128
    const int c0 = tid*4;

    const float4 xv = ld4(x + (size_t)row*CC + c0);
    const float4 xx = ld4(g_xx + (size_t)dir*BTC + (size_t)m*CC + c0);

    // ---- bf16 planes for r,k,v variants ----
    const float* maas[3] = {maar, maak, maav};
    #pragma unroll
    for (int v = 0; v < 3; ++v) {
        const float4 mv = ld4(maas[v] + c0);
        float4 a;
        a.x = fmaf(xx.x, mv.x, xv.x);
        a.y = fmaf(xx.y, mv.y, xv.y);
        a.z = fmaf(xx.z, mv.z, xv.z);
        a.w = fmaf(xx.w, mv.w, xv.w);
        uint2 hi, lo;
        bfsplit4(a, hi, lo);
        const size_t vb = (size_t)(dir*3 + v) * BTC;
        const size_t u2idx = (size_t)m*128 + tid;
        ((uint2*)(g_Ahi + vb))[u2idx] = hi;
        ((uint2*)(g_Alo + vb))[u2idx] = lo;
    }

    // ---- decay MLP ----
    const float4 mw = ld4(maa_w + c0);
    float4 vw;
    vw.x = fmaf(xx.x, mw.x, xv.x);
    vw.y = fmaf(xx.y, mw.y, xv.y);
    vw.z = fmaf(xx.z, mw.z, xv.z);
    vw.w = fmaf(xx.w, mw.w, xv.w);

    float p[16];
    #pragma unroll
    for (int j = 0; j < 16; ++j) p[j] = 0.0f;
    const float vv4[4] = {vw.x, vw.y, vw.z, vw.w};
    #pragma unroll
    for (int i = 0; i < 4; ++i) {
        const float v = vv4[i];
        const float4* wr4 = (const float4*)(w1 + (c0+i)*16);
        const float4 wa = wr4[0], wb = wr4[1], wc = wr4[2], wd = wr4[3];
        p[0]  = fmaf(v, wa.x, p[0]);  p[1]  = fmaf(v, wa.y, p[1]);
        p[2]  = fmaf(v, wa.z, p[2]);  p[3]  = fmaf(v, wa.w, p[3]);
        p[4]  = fmaf(v, wb.x, p[4]);  p[5]  = fmaf(v, wb.y, p[5]);
        p[6]  = fmaf(v, wb.z, p[6]);  p[7]  = fmaf(v, wb.w, p[7]);
        p[8]  = fmaf(v, wc.x, p[8]);  p[9]  = fmaf(v, wc.y, p[9]);
        p[10] = fmaf(v, wc.z, p[10]); p[11] = fmaf(v, wc.w, p[11]);
        p[12] = fmaf(v, wd.x, p[12]); p[13] = fmaf(v, wd.y, p[13]);
        p[14] = fmaf(v, wd.z, p[14]); p[15] = fmaf(v, wd.w, p[15]);
    }
    #pragma unroll
    for (int j = 0; j < 16; ++j) {
        #pragma unroll
        for (int off = 16; off > 0; off >>= 1)
            p[j] += __shfl_xor_sync(0xffffffffu, p[j], off);
    }
    __shared__ float ps[4][16];
    __shared__ float th[16];
    if ((tid & 31) == 0) {
        #pragma unroll
        for (int j = 0; j < 16; ++j) ps[tid >> 5][j] = p[j];
    }
    __syncthreads();
    if (tid < 16) th[tid] = tanhf(ps[0][tid] + ps[1][tid] + ps[2][tid] + ps[3][tid]);
    __syncthreads();

    float4 wv = make_float4(tdec[c0], tdec[c0+1], tdec[c0+2], tdec[c0+3]);
    #pragma unroll
    for (int j = 0; j < 16; ++j) {
        const float4 w2r = ld4(w2 + j*CC + c0);
        const float tj = th[j];
        wv.x = fmaf(tj, w2r.x, wv.x);
        wv.y = fmaf(tj, w2r.y, wv.y);
        wv.z = fmaf(tj, w2r.z, wv.z);
        wv.w = fmaf(tj, w2r.w, wv.w);
    }
    float4 d4;
    d4.x = expf(-expf(wv.x));
    d4.y = expf(-expf(wv.y));
    d4.z = expf(-expf(wv.z));
    d4.w = expf(-expf(wv.w));
    *(float4*)(g_d + (size_t)dir*BTC + (size_t)m*CC + c0) = d4;
}

// ---------------- prep: W -> bf16 hi/lo planes (8 ch/thread) ----------------
__global__ void prep_w_kernel(const float* __restrict__ Wr, const float* __restrict__ Wk,
                              const float* __restrict__ Wv, const float* __restrict__ Wo)
{
    const int idx = blockIdx.x*256 + threadIdx.x;       // over 4*CC*CC/8
    const int w = idx >> 15;                             // CC*CC/8 = 32768
    const int r = idx & 32767;
    const float* W = (w==0) ? Wr : (w==1) ? Wk : (w==2) ? Wv : Wo;
    const float4 va = ld4(W + (size_t)r*8);
    const float4 vb = ld4(W + (size_t)r*8 + 4);
    uint2 ha, la, hb, lb;
    bfsplit4(va, ha, la);
    bfsplit4(vb, hb, lb);
    ((uint4*)(g_Whi + (size_t)w*CC*CC))[r] = make_uint4(ha.x, ha.y, hb.x, hb.y);
    ((uint4*)(g_Wlo + (size_t)w*CC*CC))[r] = make_uint4(la.x, la.y, lb.x, lb.y);
}

// ---------------- bf16-split tensor-core GEMM: Out[m][n] = sum_k A[m][k]*W[n][k] ----------------
// 3-stage cp.async pipeline, XOR-swizzled smem (8 u32/row), ldmatrix frag loads.
#define BKW 8                       // u32 per row per plane (16 bf16)
#define PLANE_W (128*BKW)           // 1024 u32
#define PLANE_B (PLANE_W*4)         // 4096 B
#define STAGE_B (PLANE_B*4)         // 16384 B

__device__ __forceinline__ void cp16(uint32_t dst, const void* src) {
    asm volatile("cp.async.cg.shared.global [%0], [%1], 16;\n" :: "r"(dst), "l"(src));
}
__device__ __forceinline__ void ldsm4(uint32_t* r, uint32_t a) {
    asm volatile("ldmatrix.sync.aligned.m8n8.x4.shared.b16 {%0,%1,%2,%3}, [%4];"
        : "=r"(r[0]), "=r"(r[1]), "=r"(r[2]), "=r"(r[3]) : "r"(a));
}
__device__ __forceinline__ void ldsm2(uint32_t* r, uint32_t a) {
    asm volatile("ldmatrix.sync.aligned.m8n8.x2.shared.b16 {%0,%1}, [%2];"
        : "=r"(r[0]), "=r"(r[1]) : "r"(a));
}

__global__ __launch_bounds__(256)
void gemm_bf16_kernel(float* __restrict__ Out_ext, int a_sel, int w_sel, int out_sel, int dir)
{
    __shared__ uint32_t sm[3][4][PLANE_W];   // [stage][Ahi,Alo,Bhi,Blo] = 48KB

    const int tid = threadIdx.x;
    const int bn = blockIdx.x * 128;
    const int bm = blockIdx.y * 128;

    const uint16_t* Ah = g_Ahi + (size_t)a_sel*BTC;
    const uint16_t* Al = g_Alo + (size_t)a_sel*BTC;
    const uint16_t* Bh = g_Whi + (size_t)w_sel*CC*CC;
    const uint16_t* Bl = g_Wlo + (size_t)w_sel*CC*CC;
    float* Out;
    switch (out_sel) {
        case 0: Out = g_r + (size_t)dir*BTC; break;
        case 1: Out = g_k + (size_t)dir*BTC; break;
        case 2: Out = g_v + (size_t)dir*BTC; break;
        default: Out = Out_ext; break;
    }

    // ---- staging: one 16B chunk per plane per thread per ktile ----
    const int row  = tid >> 1;
    const int half = tid & 1;
    const int halfsw = half ^ ((row >> 2) & 1);         // XOR swizzle
    const uint16_t* pa_h = Ah + (size_t)(bm + row)*CC + half*8;
    const uint16_t* pa_l = Al + (size_t)(bm + row)*CC + half*8;
    const uint16_t* pb_h = Bh + (size_t)(bn + row)*CC + half*8;
    const uint16_t* pb_l = Bl + (size_t)(bn + row)*CC + half*8;
    const uint32_t smbase = (uint32_t)__cvta_generic_to_shared(&sm[0][0][0]);
    const uint32_t doff = (uint32_t)(row*32 + halfsw*16);

    const int lane = tid & 31;
    const int grp  = lane >> 2;
    const int qid  = lane & 3;
    const int wid  = tid >> 5;
    const int wm   = wid >> 2;
    const int wn   = wid & 3;

    // ldmatrix lane offsets (bytes within plane)
    const int selA = lane >> 3;                              // 0..3
    const int rA   = wm*64 + ((selA & 1) << 3) + (lane & 7); // + mt*16 later
    const int hA   = (selA >> 1) ^ ((rA >> 2) & 1);
    const uint32_t offA = (uint32_t)(rA*32 + hA*16);
    const int l15  = lane & 15;
    const int selB = l15 >> 3;                               // 0..1
    const int rB   = wn*32 + (l15 & 7);                      // + nt*8 later
    const int hB   = selB ^ ((rB >> 2) & 1);
    const uint32_t offB = (uint32_t)(rB*32 + hB*16);

    float c[4][4][4];
    #pragma unroll
    for (int mt = 0; mt < 4; ++mt)
        #pragma unroll
        for (int nt = 0; nt < 4; ++nt)
            #pragma unroll
            for (int e = 0; e < 4; ++e) c[mt][nt][e] = 0.0f;

    // prologue: prefetch ktiles 0,1 into stages 0,1
    #pragma unroll
    for (int kt = 0; kt < 2; ++kt) {
        const uint32_t d = smbase + kt*STAGE_B + doff;
        const int off = kt*16;
        cp16(d + 0*PLANE_B, pa_h + off);
        cp16(d + 1*PLANE_B, pa_l + off);
        cp16(d + 2*PLANE_B, pb_h + off);
        cp16(d + 3*PLANE_B, pb_l + off);
        asm volatile("cp.async.commit_group;\n");
    }

    int p = 0;
    for (int kt = 0; kt < 32; ++kt) {
        asm volatile("cp.async.wait_group 1;\n");
        __syncthreads();

        const uint32_t sb = smbase + p*STAGE_B;
        uint32_t ah[4][4], al[4][4], bh[4][2], bl[4][2];
        #pragma unroll
        for (int mt = 0; mt < 4; ++mt) ldsm4(ah[mt], sb + 0*PLANE_B + mt*512 + offA);
        #pragma unroll
        for (int mt = 0; mt < 4; ++mt) ldsm4(al[mt], sb + 1*PLANE_B + mt*512 + offA);
        #pragma unroll
        for (int nt = 0; nt < 4; ++nt) ldsm2(bh[nt], sb + 2*PLANE_B + nt*256 + offB);
        #pragma unroll
        for (int nt = 0; nt < 4; ++nt) ldsm2(bl[nt], sb + 3*PLANE_B + nt*256 + offB);

        #pragma unroll
        for (int mt = 0; mt < 4; ++mt) {
            #pragma unroll
            for (int nt = 0; nt < 4; ++nt) {
                asm volatile(
                    "mma.sync.aligned.m16n8k16.row.col.f32.bf16.bf16.f32 "
                    "{%0,%1,%2,%3}, {%4,%5,%6,%7}, {%8,%9}, {%0,%1,%2,%3};"
                    : "+f"(c[mt][nt][0]), "+f"(c[mt][nt][1]),
                      "+f"(c[mt][nt][2]), "+f"(c[mt][nt][3])
                    : "r"(ah[mt][0]), "r"(ah[mt][1]), "r"(ah[mt][2]), "r"(ah[mt][3]),
                      "r"(bh[nt][0]), "r"(bh[nt][1]));
                asm volatile(
                    "mma.sync.aligned.m16n8k16.row.col.f32.bf16.bf16.f32 "
                    "{%0,%1,%2,%3}, {%4,%5,%6,%7}, {%8,%9}, {%0,%1,%2,%3};"
                    : "+f"(c[mt][nt][0]), "+f"(c[mt][nt][1]),
                      "+f"(c[mt][nt][2]), "+f"(c[mt][nt][3])
                    : "r"(al[mt][0]), "r"(al[mt][1]), "r"(al[mt][2]), "r"(al[mt][3]),
                      "r"(bh[nt][0]), "r"(bh[nt][1]));
                asm volatile(
                    "mma.sync.aligned.m16n8k16.row.col.f32.bf16.bf16.f32 "
                    "{%0,%1,%2,%3}, {%4,%5,%6,%7}, {%8,%9}, {%0,%1,%2,%3};"
                    : "+f"(c[mt][nt][0]), "+f"(c[mt][nt][1]),
                      "+f"(c[mt][nt][2]), "+f"(c[mt][nt][3])
                    : "r"(ah[mt][0]), "r"(ah[mt][1]), "r"(ah[mt][2]), "r"(ah[mt][3]),
                      "r"(bl[nt][0]), "r"(bl[nt][1]));
            }
        }

        // prefetch ktile kt+2 into the stage consumed at iteration kt-1
        if (kt < 30) {
            int ps = p + 2; if (ps >= 3) ps -= 3;
            const uint32_t d = smbase + ps*STAGE_B + doff;
            const int off = (kt+2)*16;
            cp16(d + 0*PLANE_B, pa_h + off);
            cp16(d + 1*PLANE_B, pa_l + off);
            cp16(d + 2*PLANE_B, pb_h + off);
            cp16(d + 3*PLANE_B, pb_l + off);
        }
        asm volatile("cp.async.commit_group;\n");
        if (++p == 3) p = 0;
    }

    // epilogue
    #pragma unroll
    for (int mt = 0; mt < 4; ++mt) {
        const int rrow = bm + wm*64 + mt*16 + grp;
        #pragma unroll
        for (int nt = 0; nt < 4; ++nt) {
            const int col = bn + wn*32 + nt*8 + qid*2;
            *(float2*)(Out + (size_t)rrow*CC + col)     = make_float2(c[mt][nt][0], c[mt][nt][1]);
            *(float2*)(Out + (size_t)(rrow+8)*CC + col) = make_float2(c[mt][nt][2], c[mt][nt][3]);
        }
    }
}

// ---------------- WKV6 chunked scan ----------------
__global__ void wkv_pass1_kernel()
{
    const int gt = blockIdx.x*128 + threadIdx.x;
    const int s = gt & 15;
    const int j = s & 7, p = s >> 3;
    const int i0 = p*4;
    const int ucid = gt >> 4;
    const int cch = ucid % NCHUNK;
    const int unit = ucid / NCHUNK;
    const int h = unit & 63, b = (unit >> 6) & 7, dir = unit >> 9;

    const size_t base = (size_t)dir*BTC + (size_t)(b*TT + cch*CLEN)*CC + h*NN;
    const float* kk = g_k + base;
    const float* vv = g_v + base;
    const float* dd = g_d + base;

    float S0=0.f,S1=0.f,S2=0.f,S3=0.f, P0=1.f,P1=1.f,P2=1.f,P3=1.f;
    int off = 0;
    #pragma unroll 4
    for (int t = 0; t < CLEN; ++t, off += CC) {
        const float4 k4 = ld4(kk + off + i0);
        const float4 d4 = ld4(dd + off + i0);
        const float v = vv[off + j];
        S0 = fmaf(d4.x, S0, k4.x*v); P0 *= d4.x;
        S1 = fmaf(d4.y, S1, k4.y*v); P1 *= d4.y;
        S2 = fmaf(d4.z, S2, k4.z*v); P2 *= d4.z;
        S3 = fmaf(d4.w, S3, k4.w*v); P3 *= d4.w;
    }
    float* Mp = g_M + (size_t)ucid*64;
    Mp[(i0+0)*8 + j] = S0;
    Mp[(i0+1)*8 + j] = S1;
    Mp[(i0+2)*8 + j] = S2;
    Mp[(i0+3)*8 + j] = S3;
    if (j == 0) {
        float* Pp = g_P + (size_t)ucid*8;
        Pp[i0+0] = P0; Pp[i0+1] = P1; Pp[i0+2] = P2; Pp[i0+3] = P3;
    }
}

__global__ void wkv_pass2_kernel()
{
    const int gt = blockIdx.x*128 + threadIdx.x;   // 16384 threads
    const int s = gt & 15;
    const int j = s & 7, p = s >> 3;
    const int i0 = p*4;
    const int unit = gt >> 4;

    float S0=0.f,S1=0.f,S2=0.f,S3=0.f;
    for (int cch = 0; cch < NCHUNK; ++cch) {
        const size_t uc = (size_t)unit*NCHUNK + cch;
        float* Sp = g_S0 + uc*64;
        Sp[(i0+0)*8 + j] = S0;
        Sp[(i0+1)*8 + j] = S1;
        Sp[(i0+2)*8 + j] = S2;
        Sp[(i0+3)*8 + j] = S3;
        const float* Pp = g_P + uc*8;
        const float* Mp = g_M + uc*64;
        S0 = fmaf(Pp[i0+0], S0, Mp[(i0+0)*8 + j]);
        S1 = fmaf(Pp[i0+1], S1, Mp[(i0+1)*8 + j]);
        S2 = fmaf(Pp[i0+2], S2, Mp[(i0+2)*8 + j]);
        S3 = fmaf(Pp[i0+3], S3, Mp[(i0+3)*8 + j]);
    }
}

__global__ void wkv_pass3_kernel(const float* __restrict__ u)
{
    const int gt = blockIdx.x*128 + threadIdx.x;
    const int s = gt & 15;
    const int j = s & 7, p = s >> 3;
    const int i0 = p*4;
    const int ucid = gt >> 4;
    const int cch = ucid % NCHUNK;
    const int unit = ucid / NCHUNK;
    const int h = unit & 63, b = (unit >> 6) & 7, dir = unit >> 9;

    const float4 uu = ld4(u + h*NN + i0);
    const size_t base = (size_t)dir*BTC + (size_t)(b*TT + cch*CLEN)*CC + h*NN;
    const float* rr = g_r + base;
    const float* kk = g_k + base;
    const float* vv = g_v + base;
    const float* dd = g_d + base;
    float* yy = g_y + base;

    const float* Sp = g_S0 + (size_t)ucid*64;
    float S0 = Sp[(i0+0)*8 + j];
    float S1 = Sp[(i0+1)*8 + j];
    float S2 = Sp[(i0+2)*8 + j];
    float S3 = Sp[(i0+3)*8 + j];

    int off = 0;
    #pragma unroll 2
    for (int t = 0; t < CLEN; ++t, off += CC) {
        const float4 r4 = ld4(rr + off + i0);
        const float4 k4 = ld4(kk + off + i0);
        const float4 d4 = ld4(dd + off + i0);
        const float v = vv[off + j];
        float y = 0.f, kv, tt;
        kv = k4.x*v; tt = fmaf(uu.x, kv, S0); y = fmaf(r4.x, tt, y); S0 = fmaf(d4.x, S0, kv);
        kv = k4.y*v; tt = fmaf(uu.y, kv, S1); y = fmaf(r4.y, tt, y); S1 = fmaf(d4.y, S1, kv);
        kv = k4.z*v; tt = fmaf(uu.z, kv, S2); y = fmaf(r4.z, tt, y); S2 = fmaf(d4.z, S2, kv);
        kv = k4.w*v; tt = fmaf(uu.w, kv, S3); y = fmaf(r4.w, tt, y); S3 = fmaf(d4.w, S3, kv);
        y += __shfl_xor_sync(0xffffffffu, y, 8);
        if (p == 0) yy[off + j] = y;
    }
}

// ---------------- combine directions + layernorm -> bf16 hi/lo planes (slot 6) ----------------
__global__ void combine_ln_kernel(const float* __restrict__ lng,
                                  const float* __restrict__ lnb)
{
    const int t = blockIdx.x, b = blockIdx.y;
    const int tid = threadIdx.x;   // 128
    const int c0 = tid*4;
    const int y = t / HS, xq = t % HS;
    const int tcol = xq*HS + y;
    const int m = b*TT + t;
    const float* yr = g_y + (size_t)m*CC;
    const float* yc = g_y + (size_t)BTC + (size_t)(b*TT + tcol)*CC;

    const float4 va = ld4(yr + c0);
    const float4 vb = ld4(yc + c0);
    float4 o;
    o.x = 0.5f*(va.x + vb.x); o.y = 0.5f*(va.y + vb.y);
    o.z = 0.5f*(va.z + vb.z); o.w = 0.5f*(va.w + vb.w);
    float s  = o.x + o.y + o.z + o.w;
    float sq = o.x*o.x + o.y*o.y + o.z*o.z + o.w*o.w;
    #pragma unroll
    for (int off = 16; off > 0; off >>= 1) {
        s  += __shfl_xor_sync(0xffffffffu, s,  off);
        sq += __shfl_xor_sync(0xffffffffu, sq, off);
    }
    __shared__ float ss[4], sqs[4];
    if ((tid & 31) == 0) { ss[tid >> 5] = s; sqs[tid >> 5] = sq; }
    __syncthreads();
    s  = ss[0] + ss[1] + ss[2] + ss[3];
    sq = sqs[0] + sqs[1] + sqs[2] + sqs[3];
    const float mu = s * (1.0f/CC);
    const float var = sq * (1.0f/CC) - mu*mu;
    const float rstd = rsqrtf(var + 1e-5f);

    const float4 g4 = ld4(lng + c0);
    const float4 b4 = ld4(lnb + c0);
    float4 res;
    res.x = (o.x - mu)*rstd*g4.x + b4.x;
    res.y = (o.y - mu)*rstd*g4.y + b4.y;
    res.z = (o.z - mu)*rstd*g4.z + b4.z;
    res.w = (o.w - mu)*rstd*g4.w + b4.w;
    uint2 hi, lo;
    bfsplit4(res, hi, lo);
    const size_t u2idx = (size_t)m*128 + tid;
    ((uint2*)(g_Ahi + (size_t)6*BTC))[u2idx] = hi;
    ((uint2*)(g_Alo + (size_t)6*BTC))[u2idx] = lo;
}

// ---------------- launch ----------------
extern "C" void kernel_launch(void* const* d_in, const int* in_sizes, int n_in,
                              void* d_out, int out_size)
{
    (void)in_sizes; (void)n_in; (void)out_size;
    const float* x     = (const float*)d_in[0];
    const float* c1    = (const float*)d_in[3];
    const float* c3    = (const float*)d_in[4];
    const float* c5    = (const float*)d_in[5];
    const float* alpha = (const float*)d_in[6];
    const float* maa_w = (const float*)d_in[7];
    const float* maa_k = (const float*)d_in[8];
    const float* maa_v = (const float*)d_in[9];
    const float* maa_r = (const float*)d_in[10];
    const float* tdec  = (const float*)d_in[11];
    const float* w1    = (const float*)d_in[12];
    const float* w2    = (const float*)d_in[13];
    const float* uu    = (const float*)d_in[14];
    const float* Wr    = (const float*)d_in[15];
    const float* Wk    = (const float*)d_in[16];
    const float* Wv    = (const float*)d_in[17];
    const float* Wo    = (const float*)d_in[18];
    const float* lng   = (const float*)d_in[19];
    const float* lnb   = (const float*)d_in[20];

    prep_coef_kernel<<<1, 512>>>(c1, c3, c5, alpha);
    prep_w_kernel<<<(4*CC*CC/8)/256, 256>>>(Wr, Wk, Wv, Wo);
    conv_shift_kernel<<<dim3(HS, BB, 2), 256>>>(x);
    fused_dp_kernel<<<dim3(TT, BB, 2), 128>>>(x, maa_w, maa_r, maa_k, maa_v, tdec, w1, w2);

    const dim3 ggrid(CC/128, MM/128);   // (4, 144)
    for (int dir = 0; dir < 2; ++dir) {
        gemm_bf16_kernel<<<ggrid, 256>>>(nullptr, dir*3+0, 0, 0, dir);
        gemm_bf16_kernel<<<ggrid, 256>>>(nullptr, dir*3+1, 1, 1, dir);
        gemm_bf16_kernel<<<ggrid, 256>>>(nullptr, dir*3+2, 2, 2, dir);
    }

    wkv_pass1_kernel<<<(NUNIT*NCHUNK*16)/128, 128>>>();
    wkv_pass2_kernel<<<(NUNIT*16)/128, 128>>>();
    wkv_pass3_kernel<<<(NUNIT*NCHUNK*16)/128, 128>>>(uu);

    combine_ln_kernel<<<dim3(TT, BB), 128>>>(lng, lnb);
    gemm_bf16_kernel<<<ggrid, 256>>>((float*)d_out, 6, 3, 3, 0);
}

// round 7
// speedup vs baseline: 3.4175x; 1.1877x over previous
#include <cuda_runtime.h>
#include <cuda_bf16.h>
#include <cstdint>

#define BB 8
#define TT 2304
#define CC 512
#define HS 48
#define HH 64
#define NN 8
#define MM (BB*TT)
#define BTC (MM*CC)
#define NCHUNK 24
#define CLEN 96          // TT / NCHUNK
#define NUNIT 1024       // 2 * BB * HH
#define TP 32            // positions per fused_dp2 block

// ---------------- scratch (device globals) ----------------
__device__ float g_xx[2*BTC];
__device__ float g_r [2*BTC];
__device__ float g_k [2*BTC];
__device__ float g_v [2*BTC];
__device__ float g_d [2*BTC];
__device__ float g_y [2*BTC];
__device__ float g_coef[25*CC];      // merged 5x5 stencil per channel, [tap][c]
// bf16 hi/lo planes: A variants 0..5 = dir*3 + {r,k,v}; 6 = layernormed
__device__ uint16_t g_Ahi[7*(size_t)BTC];
__device__ uint16_t g_Alo[7*(size_t)BTC];
__device__ uint16_t g_Whi[4*CC*CC];   // 0=Wr 1=Wk 2=Wv 3=Wo
__device__ uint16_t g_Wlo[4*CC*CC];
// chunked scan scratch
__device__ float g_M [NUNIT*NCHUNK*64];
__device__ float g_P [NUNIT*NCHUNK*8];
__device__ float g_S0[NUNIT*NCHUNK*64];

__device__ __forceinline__ float4 ld4(const float* p) { return *(const float4*)p; }

__device__ __forceinline__ void bfsplit4(float4 v, uint2& hi, uint2& lo) {
    __nv_bfloat16 hx = __float2bfloat16(v.x);
    __nv_bfloat16 hy = __float2bfloat16(v.y);
    __nv_bfloat16 hz = __float2bfloat16(v.z);
    __nv_bfloat16 hw = __float2bfloat16(v.w);
    float rx = v.x - __bfloat162float(hx);
    float ry = v.y - __bfloat162float(hy);
    float rz = v.z - __bfloat162float(hz);
    float rw = v.w - __bfloat162float(hw);
    __nv_bfloat16 lx = __float2bfloat16(rx);
    __nv_bfloat16 ly = __float2bfloat16(ry);
    __nv_bfloat16 lz = __float2bfloat16(rz);
    __nv_bfloat16 lw = __float2bfloat16(rw);
    hi.x = ((uint32_t)__bfloat16_as_ushort(hy) << 16) | __bfloat16_as_ushort(hx);
    hi.y = ((uint32_t)__bfloat16_as_ushort(hw) << 16) | __bfloat16_as_ushort(hz);
    lo.x = ((uint32_t)__bfloat16_as_ushort(ly) << 16) | __bfloat16_as_ushort(lx);
    lo.y = ((uint32_t)__bfloat16_as_ushort(lw) << 16) | __bfloat16_as_ushort(lz);
}

// ---------------- merged stencil coefficients ----------------
__global__ void prep_coef_kernel(const float* __restrict__ c1,
                                 const float* __restrict__ c3,
                                 const float* __restrict__ c5,
                                 const float* __restrict__ alpha)
{
    const int c = threadIdx.x;   // 512
    const float a0 = alpha[0], a1 = alpha[1], a2 = alpha[2], a3 = alpha[3];
    #pragma unroll
    for (int i = 0; i < 5; ++i) {
        #pragma unroll
        for (int j = 0; j < 5; ++j) {
            float w = a3 * c5[c*25 + i*5 + j];
            if (i >= 1 && i <= 3 && j >= 1 && j <= 3)
                w += a2 * c3[c*9 + (i-1)*3 + (j-1)];
            if (i == 2 && j == 2)
                w += a1 * c1[c] + a0 - 1.0f;    // -1: xx = sh - x
            g_coef[(i*5+j)*CC + c] = w;
        }
    }
}

// ---------------- conv shift (float4 channels) ----------------
__global__ void conv_shift_kernel(const float* __restrict__ x)
{
    const int u   = blockIdx.x;
    const int b   = blockIdx.y;
    const int dir = blockIdx.z;
    const int c0  = (threadIdx.x & 127) * 4;     // 4 channels per thread
    const int qh  = threadIdx.x >> 7;
    const float* xb = x + (size_t)b*TT*CC;
    float* xxb = g_xx + (size_t)dir*BTC + (size_t)b*TT*CC;

    for (int q = qh; q < HS; q += 2) {
        float4 acc = make_float4(0.f, 0.f, 0.f, 0.f);
        #pragma unroll
        for (int i = 0; i < 5; ++i) {
            const int uu = u + i - 2;
            if (uu < 0 || uu >= HS) continue;
            #pragma unroll
            for (int j = 0; j < 5; ++j) {
                const int qq = q + j - 2;
                if (qq < 0 || qq >= HS) continue;
                const int idx = dir ? (qq*HS + uu) : (uu*HS + qq);
                const float4 cf = ld4(g_coef + (i*5+j)*CC + c0);
                const float4 xv = ld4(xb + (size_t)idx*CC + c0);
                acc.x = fmaf(cf.x, xv.x, acc.x);
                acc.y = fmaf(cf.y, xv.y, acc.y);
                acc.z = fmaf(cf.z, xv.z, acc.z);
                acc.w = fmaf(cf.w, xv.w, acc.w);
            }
        }
        *(float4*)(xxb + (size_t)(u*HS + q)*CC + c0) = acc;
    }
}

// ---------------- fused decay + bf16 plane prep, v2 (w1/w2 amortized in smem) ----------------
// Block: 256 threads = 32 positions x 8 channel-slices. One streaming pass over x+xx:
// writes the 3 bf16 A-variant plane pairs AND computes decay d.
__global__ __launch_bounds__(256)
void fused_dp2_kernel(const float* __restrict__ x,
                      const float* __restrict__ maa_w,
                      const float* __restrict__ maar,
                      const float* __restrict__ maak,
                      const float* __restrict__ maav,
                      const float* __restrict__ tdec,
                      const float* __restrict__ w1,   // [C][16]
                      const float* __restrict__ w2)   // [16][C]
{
    __shared__ float w1s[16*CC];     // w1 transposed [j][c]; reused for w2 [j][c]
    __shared__ float Hs[TP][16];

    const int tid = threadIdx.x;
    const int t0  = blockIdx.x * TP;
    const int b   = blockIdx.y;
    const int dir = blockIdx.z;

    // stage w1 transposed
    for (int idx = tid; idx < 16*CC; idx += 256) {
        const int c = idx >> 4, j = idx & 15;
        w1s[j*CC + c] = w1[c*16 + j];
    }
    __syncthreads();

    const int p = tid >> 3;          // 0..31 position
    const int s = tid & 7;           // 0..7 channel slice
    const int t = t0 + p;
    const int m = b*TT + t;
    const int row = dir ? (b*TT + (t % HS)*HS + (t / HS)) : m;
    const size_t xxbase = (size_t)dir*BTC + (size_t)m*CC;
    const size_t u2base = (size_t)m*128;

    float h[16];
    #pragma unroll
    for (int j = 0; j < 16; ++j) h[j] = 0.0f;

    #pragma unroll 4
    for (int i = 0; i < 16; ++i) {
        const int c = (i*8 + s)*4;           // interleaved: lanes of same p contiguous
        const float4 xv = ld4(x + (size_t)row*CC + c);
        const float4 xx = ld4(g_xx + xxbase + c);

        // bf16 planes for r,k,v
        {
            const float4 mr = ld4(maar + c);
            float4 a;
            a.x = fmaf(xx.x, mr.x, xv.x); a.y = fmaf(xx.y, mr.y, xv.y);
            a.z = fmaf(xx.z, mr.z, xv.z); a.w = fmaf(xx.w, mr.w, xv.w);
            uint2 hi, lo; bfsplit4(a, hi, lo);
            const size_t vb = (size_t)(dir*3 + 0) * BTC;
            ((uint2*)(g_Ahi + vb))[u2base + c/4] = hi;
            ((uint2*)(g_Alo + vb))[u2base + c/4] = lo;
        }
        {
            const float4 mk = ld4(maak + c);
            float4 a;
            a.x = fmaf(xx.x, mk.x, xv.x); a.y = fmaf(xx.y, mk.y, xv.y);
            a.z = fmaf(xx.z, mk.z, xv.z); a.w = fmaf(xx.w, mk.w, xv.w);
            uint2 hi, lo; bfsplit4(a, hi, lo);
            const size_t vb = (size_t)(dir*3 + 1) * BTC;
            ((uint2*)(g_Ahi + vb))[u2base + c/4] = hi;
            ((uint2*)(g_Alo + vb))[u2base + c/4] = lo;
        }
        {
            const float4 mv = ld4(maav + c);
            float4 a;
            a.x = fmaf(xx.x, mv.x, xv.x); a.y = fmaf(xx.y, mv.y, xv.y);
            a.z = fmaf(xx.z, mv.z, xv.z); a.w = fmaf(xx.w, mv.w, xv.w);
            uint2 hi, lo; bfsplit4(a, hi, lo);
            const size_t vb = (size_t)(dir*3 + 2) * BTC;
            ((uint2*)(g_Ahi + vb))[u2base + c/4] = hi;
            ((uint2*)(g_Alo + vb))[u2base + c/4] = lo;
        }

        // xw for decay MLP
        const float4 mw = ld4(maa_w + c);
        const float v0 = fmaf(xx.x, mw.x, xv.x);
        const float v1 = fmaf(xx.y, mw.y, xv.y);
        const float v2 = fmaf(xx.z, mw.z, xv.z);
        const float v3 = fmaf(xx.w, mw.w, xv.w);
        #pragma unroll
        for (int j = 0; j < 16; ++j) {
            const float* wr = w1s + j*CC + c;
            h[j] = fmaf(v0, wr[0], h[j]);
            h[j] = fmaf(v1, wr[1], h[j]);
            h[j] = fmaf(v2, wr[2], h[j]);
            h[j] = fmaf(v3, wr[3], h[j]);
        }
    }

    // reduce over 8 slices (adjacent lanes) and tanh
    #pragma unroll
    for (int j = 0; j < 16; ++j) {
        h[j] += __shfl_xor_sync(0xffffffffu, h[j], 1);
        h[j] += __shfl_xor_sync(0xffffffffu, h[j], 2);
        h[j] += __shfl_xor_sync(0xffffffffu, h[j], 4);
    }
    if (s == 0) {
        #pragma unroll
        for (int j = 0; j < 16; ++j) Hs[p][j] = tanhf(h[j]);
    }
    __syncthreads();

    // stage w2 (already [j][c]) into the same smem buffer
    for (int idx4 = tid; idx4 < 16*CC/4; idx4 += 256)
        ((float4*)w1s)[idx4] = ((const float4*)w2)[idx4];
    __syncthreads();

    // expansion: thread owns 2 channels across all TP positions
    const int c0 = tid*2;
    float w2a[16], w2b[16];
    #pragma unroll
    for (int j = 0; j < 16; ++j) { w2a[j] = w1s[j*CC + c0]; w2b[j] = w1s[j*CC + c0 + 1]; }
    const float td0 = tdec[c0], td1 = tdec[c0+1];
    float* dbase = g_d + (size_t)dir*BTC + (size_t)(b*TT + t0)*CC + c0;
    #pragma unroll 4
    for (int pp = 0; pp < TP; ++pp) {
        float a0 = td0, a1 = td1;
        #pragma unroll
        for (int j = 0; j < 16; ++j) {
            const float hj = Hs[pp][j];
            a0 = fmaf(hj, w2a[j], a0);
            a1 = fmaf(hj, w2b[j], a1);
        }
        *(float2*)(dbase + (size_t)pp*CC) = make_float2(expf(-expf(a0)), expf(-expf(a1)));
    }
}

// ---------------- prep: W -> bf16 hi/lo planes (8 ch/thread) ----------------
__global__ void prep_w_kernel(const float* __restrict__ Wr, const float* __restrict__ Wk,
                              const float* __restrict__ Wv, const float* __restrict__ Wo)
{
    const int idx = blockIdx.x*256 + threadIdx.x;       // over 4*CC*CC/8
    const int w = idx >> 15;                             // CC*CC/8 = 32768
    const int r = idx & 32767;
    const float* W = (w==0) ? Wr : (w==1) ? Wk : (w==2) ? Wv : Wo;
    const float4 va = ld4(W + (size_t)r*8);
    const float4 vb = ld4(W + (size_t)r*8 + 4);
    uint2 ha, la, hb, lb;
    bfsplit4(va, ha, la);
    bfsplit4(vb, hb, lb);
    ((uint4*)(g_Whi + (size_t)w*CC*CC))[r] = make_uint4(ha.x, ha.y, hb.x, hb.y);
    ((uint4*)(g_Wlo + (size_t)w*CC*CC))[r] = make_uint4(la.x, la.y, lb.x, lb.y);
}

// ---------------- bf16-split tensor-core GEMM: Out[m][n] = sum_k A[m][k]*W[n][k] ----------------
// 3-stage cp.async pipeline, XOR-swizzled smem (8 u32/row), ldmatrix frag loads.
#define BKW 8                       // u32 per row per plane (16 bf16)
#define PLANE_W (128*BKW)           // 1024 u32
#define PLANE_B (PLANE_W*4)         // 4096 B
#define STAGE_B (PLANE_B*4)         // 16384 B

__device__ __forceinline__ void cp16(uint32_t dst, const void* src) {
    asm volatile("cp.async.cg.shared.global [%0], [%1], 16;\n" :: "r"(dst), "l"(src));
}
__device__ __forceinline__ void ldsm4(uint32_t* r, uint32_t a) {
    asm volatile("ldmatrix.sync.aligned.m8n8.x4.shared.b16 {%0,%1,%2,%3}, [%4];"
        : "=r"(r[0]), "=r"(r[1]), "=r"(r[2]), "=r"(r[3]) : "r"(a));
}
__device__ __forceinline__ void ldsm2(uint32_t* r, uint32_t a) {
    asm volatile("ldmatrix.sync.aligned.m8n8.x2.shared.b16 {%0,%1}, [%2];"
        : "=r"(r[0]), "=r"(r[1]) : "r"(a));
}

__global__ __launch_bounds__(256)
void gemm_bf16_kernel(float* __restrict__ Out_ext, int a_sel, int w_sel, int out_sel, int dir)
{
    __shared__ uint32_t sm[3][4][PLANE_W];   // [stage][Ahi,Alo,Bhi,Blo] = 48KB

    const int tid = threadIdx.x;
    const int bn = blockIdx.x * 128;
    const int bm = blockIdx.y * 128;

    const uint16_t* Ah = g_Ahi + (size_t)a_sel*BTC;
    const uint16_t* Al = g_Alo + (size_t)a_sel*BTC;
    const uint16_t* Bh = g_Whi + (size_t)w_sel*CC*CC;
    const uint16_t* Bl = g_Wlo + (size_t)w_sel*CC*CC;
    float* Out;
    switch (out_sel) {
        case 0: Out = g_r + (size_t)dir*BTC; break;
        case 1: Out = g_k + (size_t)dir*BTC; break;
        case 2: Out = g_v + (size_t)dir*BTC; break;
        default: Out = Out_ext; break;
    }

    // ---- staging: one 16B chunk per plane per thread per ktile ----
    const int row  = tid >> 1;
    const int half = tid & 1;
    const int halfsw = half ^ ((row >> 2) & 1);         // XOR swizzle
    const uint16_t* pa_h = Ah + (size_t)(bm + row)*CC + half*8;
    const uint16_t* pa_l = Al + (size_t)(bm + row)*CC + half*8;
    const uint16_t* pb_h = Bh + (size_t)(bn + row)*CC + half*8;
    const uint16_t* pb_l = Bl + (size_t)(bn + row)*CC + half*8;
    const uint32_t smbase = (uint32_t)__cvta_generic_to_shared(&sm[0][0][0]);
    const uint32_t doff = (uint32_t)(row*32 + halfsw*16);

    const int lane = tid & 31;
    const int grp  = lane >> 2;
    const int qid  = lane & 3;
    const int wid  = tid >> 5;
    const int wm   = wid >> 2;
    const int wn   = wid & 3;

    // ldmatrix lane offsets (bytes within plane)
    const int selA = lane >> 3;                              // 0..3
    const int rA   = wm*64 + ((selA & 1) << 3) + (lane & 7); // + mt*16 later
    const int hA   = (selA >> 1) ^ ((rA >> 2) & 1);
    const uint32_t offA = (uint32_t)(rA*32 + hA*16);
    const int l15  = lane & 15;
    const int selB = l15 >> 3;                               // 0..1
    const int rB   = wn*32 + (l15 & 7);                      // + nt*8 later
    const int hB   = selB ^ ((rB >> 2) & 1);
    const uint32_t offB = (uint32_t)(rB*32 + hB*16);

    float c[4][4][4];
    #pragma unroll
    for (int mt = 0; mt < 4; ++mt)
        #pragma unroll
        for (int nt = 0; nt < 4; ++nt)
            #pragma unroll
            for (int e = 0; e < 4; ++e) c[mt][nt][e] = 0.0f;

    // prologue: prefetch ktiles 0,1 into stages 0,1
    #pragma unroll
    for (int kt = 0; kt < 2; ++kt) {
        const uint32_t d = smbase + kt*STAGE_B + doff;
        const int off = kt*16;
        cp16(d + 0*PLANE_B, pa_h + off);
        cp16(d + 1*PLANE_B, pa_l + off);
        cp16(d + 2*PLANE_B, pb_h + off);
        cp16(d + 3*PLANE_B, pb_l + off);
        asm volatile("cp.async.commit_group;\n");
    }

    int p = 0;
    for (int kt = 0; kt < 32; ++kt) {
        asm volatile("cp.async.wait_group 1;\n");
        __syncthreads();

        const uint32_t sb = smbase + p*STAGE_B;
        uint32_t ah[4][4], al[4][4], bh[4][2], bl[4][2];
        #pragma unroll
        for (int mt = 0; mt < 4; ++mt) ldsm4(ah[mt], sb + 0*PLANE_B + mt*512 + offA);
        #pragma unroll
        for (int mt = 0; mt < 4; ++mt) ldsm4(al[mt], sb + 1*PLANE_B + mt*512 + offA);
        #pragma unroll
        for (int nt = 0; nt < 4; ++nt) ldsm2(bh[nt], sb + 2*PLANE_B + nt*256 + offB);
        #pragma unroll
        for (int nt = 0; nt < 4; ++nt) ldsm2(bl[nt], sb + 3*PLANE_B + nt*256 + offB);

        #pragma unroll
        for (int mt = 0; mt < 4; ++mt) {
            #pragma unroll
            for (int nt = 0; nt < 4; ++nt) {
                asm volatile(
                    "mma.sync.aligned.m16n8k16.row.col.f32.bf16.bf16.f32 "
                    "{%0,%1,%2,%3}, {%4,%5,%6,%7}, {%8,%9}, {%0,%1,%2,%3};"
                    : "+f"(c[mt][nt][0]), "+f"(c[mt][nt][1]),
                      "+f"(c[mt][nt][2]), "+f"(c[mt][nt][3])
                    : "r"(ah[mt][0]), "r"(ah[mt][1]), "r"(ah[mt][2]), "r"(ah[mt][3]),
                      "r"(bh[nt][0]), "r"(bh[nt][1]));
                asm volatile(
                    "mma.sync.aligned.m16n8k16.row.col.f32.bf16.bf16.f32 "
                    "{%0,%1,%2,%3}, {%4,%5,%6,%7}, {%8,%9}, {%0,%1,%2,%3};"
                    : "+f"(c[mt][nt][0]), "+f"(c[mt][nt][1]),
                      "+f"(c[mt][nt][2]), "+f"(c[mt][nt][3])
                    : "r"(al[mt][0]), "r"(al[mt][1]), "r"(al[mt][2]), "r"(al[mt][3]),
                      "r"(bh[nt][0]), "r"(bh[nt][1]));
                asm volatile(
                    "mma.sync.aligned.m16n8k16.row.col.f32.bf16.bf16.f32 "
                    "{%0,%1,%2,%3}, {%4,%5,%6,%7}, {%8,%9}, {%0,%1,%2,%3};"
                    : "+f"(c[mt][nt][0]), "+f"(c[mt][nt][1]),
                      "+f"(c[mt][nt][2]), "+f"(c[mt][nt][3])
                    : "r"(ah[mt][0]), "r"(ah[mt][1]), "r"(ah[mt][2]), "r"(ah[mt][3]),
                      "r"(bl[nt][0]), "r"(bl[nt][1]));
            }
        }

        // prefetch ktile kt+2 into the stage consumed at iteration kt-1
        if (kt < 30) {
            int ps = p + 2; if (ps >= 3) ps -= 3;
            const uint32_t d = smbase + ps*STAGE_B + doff;
            const int off = (kt+2)*16;
            cp16(d + 0*PLANE_B, pa_h + off);
            cp16(d + 1*PLANE_B, pa_l + off);
            cp16(d + 2*PLANE_B, pb_h + off);
            cp16(d + 3*PLANE_B, pb_l + off);
        }
        asm volatile("cp.async.commit_group;\n");
        if (++p == 3) p = 0;
    }

    // epilogue
    #pragma unroll
    for (int mt = 0; mt < 4; ++mt) {
        const int rrow = bm + wm*64 + mt*16 + grp;
        #pragma unroll
        for (int nt = 0; nt < 4; ++nt) {
            const int col = bn + wn*32 + nt*8 + qid*2;
            *(float2*)(Out + (size_t)rrow*CC + col)     = make_float2(c[mt][nt][0], c[mt][nt][1]);
            *(float2*)(Out + (size_t)(rrow+8)*CC + col) = make_float2(c[mt][nt][2], c[mt][nt][3]);
        }
    }
}

// ---------------- WKV6 chunked scan ----------------
__global__ void wkv_pass1_kernel()
{
    const int gt = blockIdx.x*128 + threadIdx.x;
    const int s = gt & 15;
    const int j = s & 7, p = s >> 3;
    const int i0 = p*4;
    const int ucid = gt >> 4;
    const int cch = ucid % NCHUNK;
    const int unit = ucid / NCHUNK;
    const int h = unit & 63, b = (unit >> 6) & 7, dir = unit >> 9;

    const size_t base = (size_t)dir*BTC + (size_t)(b*TT + cch*CLEN)*CC + h*NN;
    const float* kk = g_k + base;
    const float* vv = g_v + base;
    const float* dd = g_d + base;

    float S0=0.f,S1=0.f,S2=0.f,S3=0.f, P0=1.f,P1=1.f,P2=1.f,P3=1.f;
    int off = 0;
    #pragma unroll 4
    for (int t = 0; t < CLEN; ++t, off += CC) {
        const float4 k4 = ld4(kk + off + i0);
        const float4 d4 = ld4(dd + off + i0);
        const float v = vv[off + j];
        S0 = fmaf(d4.x, S0, k4.x*v); P0 *= d4.x;
        S1 = fmaf(d4.y, S1, k4.y*v); P1 *= d4.y;
        S2 = fmaf(d4.z, S2, k4.z*v); P2 *= d4.z;
        S3 = fmaf(d4.w, S3, k4.w*v); P3 *= d4.w;
    }
    float* Mp = g_M + (size_t)ucid*64;
    Mp[(i0+0)*8 + j] = S0;
    Mp[(i0+1)*8 + j] = S1;
    Mp[(i0+2)*8 + j] = S2;
    Mp[(i0+3)*8 + j] = S3;
    if (j == 0) {
        float* Pp = g_P + (size_t)ucid*8;
        Pp[i0+0] = P0; Pp[i0+1] = P1; Pp[i0+2] = P2; Pp[i0+3] = P3;
    }
}

__global__ void wkv_pass2_kernel()
{
    const int gt = blockIdx.x*128 + threadIdx.x;   // 16384 threads
    const int s = gt & 15;
    const int j = s & 7, p = s >> 3;
    const int i0 = p*4;
    const int unit = gt >> 4;

    float S0=0.f,S1=0.f,S2=0.f,S3=0.f;
    for (int cch = 0; cch < NCHUNK; ++cch) {
        const size_t uc = (size_t)unit*NCHUNK + cch;
        float* Sp = g_S0 + uc*64;
        Sp[(i0+0)*8 + j] = S0;
        Sp[(i0+1)*8 + j] = S1;
        Sp[(i0+2)*8 + j] = S2;
        Sp[(i0+3)*8 + j] = S3;
        const float* Pp = g_P + uc*8;
        const float* Mp = g_M + uc*64;
        S0 = fmaf(Pp[i0+0], S0, Mp[(i0+0)*8 + j]);
        S1 = fmaf(Pp[i0+1], S1, Mp[(i0+1)*8 + j]);
        S2 = fmaf(Pp[i0+2], S2, Mp[(i0+2)*8 + j]);
        S3 = fmaf(Pp[i0+3], S3, Mp[(i0+3)*8 + j]);
    }
}

__global__ void wkv_pass3_kernel(const float* __restrict__ u)
{
    const int gt = blockIdx.x*128 + threadIdx.x;
    const int s = gt & 15;
    const int j = s & 7, p = s >> 3;
    const int i0 = p*4;
    const int ucid = gt >> 4;
    const int cch = ucid % NCHUNK;
    const int unit = ucid / NCHUNK;
    const int h = unit & 63, b = (unit >> 6) & 7, dir = unit >> 9;

    const float4 uu = ld4(u + h*NN + i0);
    const size_t base = (size_t)dir*BTC + (size_t)(b*TT + cch*CLEN)*CC + h*NN;
    const float* rr = g_r + base;
    const float* kk = g_k + base;
    const float* vv = g_v + base;
    const float* dd = g_d + base;
    float* yy = g_y + base;

    const float* Sp = g_S0 + (size_t)ucid*64;
    float S0 = Sp[(i0+0)*8 + j];
    float S1 = Sp[(i0+1)*8 + j];
    float S2 = Sp[(i0+2)*8 + j];
    float S3 = Sp[(i0+3)*8 + j];

    int off = 0;
    #pragma unroll 2
    for (int t = 0; t < CLEN; ++t, off += CC) {
        const float4 r4 = ld4(rr + off + i0);
        const float4 k4 = ld4(kk + off + i0);
        const float4 d4 = ld4(dd + off + i0);
        const float v = vv[off + j];
        float y = 0.f, kv, tt;
        kv = k4.x*v; tt = fmaf(uu.x, kv, S0); y = fmaf(r4.x, tt, y); S0 = fmaf(d4.x, S0, kv);
        kv = k4.y*v; tt = fmaf(uu.y, kv, S1); y = fmaf(r4.y, tt, y); S1 = fmaf(d4.y, S1, kv);
        kv = k4.z*v; tt = fmaf(uu.z, kv, S2); y = fmaf(r4.z, tt, y); S2 = fmaf(d4.z, S2, kv);
        kv = k4.w*v; tt = fmaf(uu.w, kv, S3); y = fmaf(r4.w, tt, y); S3 = fmaf(d4.w, S3, kv);
        y += __shfl_xor_sync(0xffffffffu, y, 8);
        if (p == 0) yy[off + j] = y;
    }
}

// ---------------- combine directions + layernorm -> bf16 hi/lo planes (slot 6) ----------------
__global__ void combine_ln_kernel(const float* __restrict__ lng,
                                  const float* __restrict__ lnb)
{
    const int t = blockIdx.x, b = blockIdx.y;
    const int tid = threadIdx.x;   // 128
    const int c0 = tid*4;
    const int y = t / HS, xq = t % HS;
    const int tcol = xq*HS + y;
    const int m = b*TT + t;
    const float* yr = g_y + (size_t)m*CC;
    const float* yc = g_y + (size_t)BTC + (size_t)(b*TT + tcol)*CC;

    const float4 va = ld4(yr + c0);
    const float4 vb = ld4(yc + c0);
    float4 o;
    o.x = 0.5f*(va.x + vb.x); o.y = 0.5f*(va.y + vb.y);
    o.z = 0.5f*(va.z + vb.z); o.w = 0.5f*(va.w + vb.w);
    float s  = o.x + o.y + o.z + o.w;
    float sq = o.x*o.x + o.y*o.y + o.z*o.z + o.w*o.w;
    #pragma unroll
    for (int off = 16; off > 0; off >>= 1) {
        s  += __shfl_xor_sync(0xffffffffu, s,  off);
        sq += __shfl_xor_sync(0xffffffffu, sq, off);
    }
    __shared__ float ss[4], sqs[4];
    if ((tid & 31) == 0) { ss[tid >> 5] = s; sqs[tid >> 5] = sq; }
    __syncthreads();
    s  = ss[0] + ss[1] + ss[2] + ss[3];
    sq = sqs[0] + sqs[1] + sqs[2] + sqs[3];
    const float mu = s * (1.0f/CC);
    const float var = sq * (1.0f/CC) - mu*mu;
    const float rstd = rsqrtf(var + 1e-5f);

    const float4 g4 = ld4(lng + c0);
    const float4 b4 = ld4(lnb + c0);
    float4 res;
    res.x = (o.x - mu)*rstd*g4.x + b4.x;
    res.y = (o.y - mu)*rstd*g4.y + b4.y;
    res.z = (o.z - mu)*rstd*g4.z + b4.z;
    res.w = (o.w - mu)*rstd*g4.w + b4.w;
    uint2 hi, lo;
    bfsplit4(res, hi, lo);
    const size_t u2idx = (size_t)m*128 + tid;
    ((uint2*)(g_Ahi + (size_t)6*BTC))[u2idx] = hi;
    ((uint2*)(g_Alo + (size_t)6*BTC))[u2idx] = lo;
}

// ---------------- launch ----------------
extern "C" void kernel_launch(void* const* d_in, const int* in_sizes, int n_in,
                              void* d_out, int out_size)
{
    (void)in_sizes; (void)n_in; (void)out_size;
    const float* x     = (const float*)d_in[0];
    const float* c1    = (const float*)d_in[3];
    const float* c3    = (const float*)d_in[4];
    const float* c5    = (const float*)d_in[5];
    const float* alpha = (const float*)d_in[6];
    const float* maa_w = (const float*)d_in[7];
    const float* maa_k = (const float*)d_in[8];
    const float* maa_v = (const float*)d_in[9];
    const float* maa_r = (const float*)d_in[10];
    const float* tdec  = (const float*)d_in[11];
    const float* w1    = (const float*)d_in[12];
    const float* w2    = (const float*)d_in[13];
    const float* uu    = (const float*)d_in[14];
    const float* Wr    = (const float*)d_in[15];
    const float* Wk    = (const float*)d_in[16];
    const float* Wv    = (const float*)d_in[17];
    const float* Wo    = (const float*)d_in[18];
    const float* lng   = (const float*)d_in[19];
    const float* lnb   = (const float*)d_in[20];

    prep_coef_kernel<<<1, 512>>>(c1, c3, c5, alpha);
    prep_w_kernel<<<(4*CC*CC/8)/256, 256>>>(Wr, Wk, Wv, Wo);
    conv_shift_kernel<<<dim3(HS, BB, 2), 256>>>(x);
    fused_dp2_kernel<<<dim3(TT/TP, BB, 2), 256>>>(x, maa_w, maa_r, maa_k, maa_v, tdec, w1, w2);

    const dim3 ggrid(CC/128, MM/128);   // (4, 144)
    for (int dir = 0; dir < 2; ++dir) {
        gemm_bf16_kernel<<<ggrid, 256>>>(nullptr, dir*3+0, 0, 0, dir);
        gemm_bf16_kernel<<<ggrid, 256>>>(nullptr, dir*3+1, 1, 1, dir);
        gemm_bf16_kernel<<<ggrid, 256>>>(nullptr, dir*3+2, 2, 2, dir);
    }

    wkv_pass1_kernel<<<(NUNIT*NCHUNK*16)/128, 128>>>();
    wkv_pass2_kernel<<<(NUNIT*16)/128, 128>>>();
    wkv_pass3_kernel<<<(NUNIT*NCHUNK*16)/128, 128>>>(uu);

    combine_ln_kernel<<<dim3(TT, BB), 128>>>(lng, lnb);
    gemm_bf16_kernel<<<ggrid, 256>>>((float*)d_out, 6, 3, 3, 0);
}

// round 8
// speedup vs baseline: 3.5874x; 1.0497x over previous
#include <cuda_runtime.h>
#include <cuda_bf16.h>
#include <cstdint>

#define BB 8
#define TT 2304
#define CC 512
#define HS 48
#define HH 64
#define NN 8
#define MM (BB*TT)
#define BTC (MM*CC)
#define NCHUNK 24
#define CLEN 96          // TT / NCHUNK
#define NUNIT 1024       // 2 * BB * HH
#define TP 32            // positions per fused_dp2 block

// ---------------- scratch (device globals) ----------------
__device__ float g_xx[2*BTC];
__device__ float g_r [2*BTC];
__device__ float g_k [2*BTC];
__device__ float g_v [2*BTC];
__device__ float g_d [2*BTC];
__device__ float g_y [2*BTC];
__device__ float g_coef[25*CC];      // merged 5x5 stencil per channel, [tap][c]
// bf16 hi/lo planes: A variants 0..5 = dir*3 + {r,k,v}; 6 = layernormed
__device__ uint16_t g_Ahi[7*(size_t)BTC];
__device__ uint16_t g_Alo[7*(size_t)BTC];
__device__ uint16_t g_Whi[4*CC*CC];   // 0=Wr 1=Wk 2=Wv 3=Wo
__device__ uint16_t g_Wlo[4*CC*CC];
// chunked scan scratch
__device__ float g_M [NUNIT*NCHUNK*64];
__device__ float g_P [NUNIT*NCHUNK*8];
__device__ float g_S0[NUNIT*NCHUNK*64];

__device__ __forceinline__ float4 ld4(const float* p) { return *(const float4*)p; }

__device__ __forceinline__ void bfsplit4(float4 v, uint2& hi, uint2& lo) {
    __nv_bfloat16 hx = __float2bfloat16(v.x);
    __nv_bfloat16 hy = __float2bfloat16(v.y);
    __nv_bfloat16 hz = __float2bfloat16(v.z);
    __nv_bfloat16 hw = __float2bfloat16(v.w);
    float rx = v.x - __bfloat162float(hx);
    float ry = v.y - __bfloat162float(hy);
    float rz = v.z - __bfloat162float(hz);
    float rw = v.w - __bfloat162float(hw);
    __nv_bfloat16 lx = __float2bfloat16(rx);
    __nv_bfloat16 ly = __float2bfloat16(ry);
    __nv_bfloat16 lz = __float2bfloat16(rz);
    __nv_bfloat16 lw = __float2bfloat16(rw);
    hi.x = ((uint32_t)__bfloat16_as_ushort(hy) << 16) | __bfloat16_as_ushort(hx);
    hi.y = ((uint32_t)__bfloat16_as_ushort(hw) << 16) | __bfloat16_as_ushort(hz);
    lo.x = ((uint32_t)__bfloat16_as_ushort(ly) << 16) | __bfloat16_as_ushort(lx);
    lo.y = ((uint32_t)__bfloat16_as_ushort(lw) << 16) | __bfloat16_as_ushort(lz);
}

// ---------------- merged stencil coefficients ----------------
__global__ void prep_coef_kernel(const float* __restrict__ c1,
                                 const float* __restrict__ c3,
                                 const float* __restrict__ c5,
                                 const float* __restrict__ alpha)
{
    const int c = threadIdx.x;   // 512
    const float a0 = alpha[0], a1 = alpha[1], a2 = alpha[2], a3 = alpha[3];
    #pragma unroll
    for (int i = 0; i < 5; ++i) {
        #pragma unroll
        for (int j = 0; j < 5; ++j) {
            float w = a3 * c5[c*25 + i*5 + j];
            if (i >= 1 && i <= 3 && j >= 1 && j <= 3)
                w += a2 * c3[c*9 + (i-1)*3 + (j-1)];
            if (i == 2 && j == 2)
                w += a1 * c1[c] + a0 - 1.0f;    // -1: xx = sh - x
            g_coef[(i*5+j)*CC + c] = w;
        }
    }
}

// ---------------- conv shift v2: register-window stencil ----------------
// 8-q chunks: per i-row, 12-wide float4 x window in registers; taps reuse it.
__global__ __launch_bounds__(256)
void conv_shift2_kernel(const float* __restrict__ x)
{
    const int u   = blockIdx.x;
    const int b   = blockIdx.y;
    const int dir = blockIdx.z;
    const int c0  = (threadIdx.x & 127) * 4;
    const int qh  = threadIdx.x >> 7;
    const float* xb = x + (size_t)b*TT*CC;
    float* xxb = g_xx + (size_t)dir*BTC + (size_t)b*TT*CC;

    for (int ch = 0; ch < 3; ++ch) {
        const int q0 = qh*24 + ch*8;
        float4 acc[8];
        #pragma unroll
        for (int qi = 0; qi < 8; ++qi) acc[qi] = make_float4(0.f, 0.f, 0.f, 0.f);

        #pragma unroll
        for (int i = 0; i < 5; ++i) {
            const int uu = u + i - 2;
            if (uu < 0 || uu >= HS) continue;
            float4 xwin[12];
            #pragma unroll
            for (int t = 0; t < 12; ++t) {
                const int qq = q0 - 2 + t;
                if (qq >= 0 && qq < HS) {
                    const int idx = dir ? (qq*HS + uu) : (uu*HS + qq);
                    xwin[t] = ld4(xb + (size_t)idx*CC + c0);
                } else {
                    xwin[t] = make_float4(0.f, 0.f, 0.f, 0.f);
                }
            }
            #pragma unroll
            for (int j = 0; j < 5; ++j) {
                const float4 cf = ld4(g_coef + (i*5+j)*CC + c0);
                #pragma unroll
                for (int qi = 0; qi < 8; ++qi) {
                    const float4 xv = xwin[qi + j];
                    acc[qi].x = fmaf(cf.x, xv.x, acc[qi].x);
                    acc[qi].y = fmaf(cf.y, xv.y, acc[qi].y);
                    acc[qi].z = fmaf(cf.z, xv.z, acc[qi].z);
                    acc[qi].w = fmaf(cf.w, xv.w, acc[qi].w);
                }
            }
        }
        #pragma unroll
        for (int qi = 0; qi < 8; ++qi)
            *(float4*)(xxb + (size_t)(u*HS + q0 + qi)*CC + c0) = acc[qi];
    }
}

// ---------------- fused decay + bf16 plane prep, v2.1 ----------------
__global__ __launch_bounds__(256)
void fused_dp2_kernel(const float* __restrict__ x,
                      const float* __restrict__ maa_w,
                      const float* __restrict__ maar,
                      const float* __restrict__ maak,
                      const float* __restrict__ maav,
                      const float* __restrict__ tdec,
                      const float* __restrict__ w1,   // [C][16]
                      const float* __restrict__ w2)   // [16][C]
{
    __shared__ float w1s[16*CC];     // w1 transposed [j][c]; reused for w2 [j][c]
    __shared__ float maas[4*CC];     // r,k,v,w
    __shared__ float Hs[TP][16];

    const int tid = threadIdx.x;
    const int t0  = blockIdx.x * TP;
    const int b   = blockIdx.y;
    const int dir = blockIdx.z;

    // stage w1 transposed + maa vectors
    for (int idx = tid; idx < 16*CC; idx += 256) {
        const int c = idx >> 4, j = idx & 15;
        w1s[j*CC + c] = w1[c*16 + j];
    }
    if (tid < 128) {
        ((float4*)maas)[tid]           = ld4(maar + tid*4);
        ((float4*)(maas + CC))[tid]    = ld4(maak + tid*4);
        ((float4*)(maas + 2*CC))[tid]  = ld4(maav + tid*4);
        ((float4*)(maas + 3*CC))[tid]  = ld4(maa_w + tid*4);
    }
    __syncthreads();

    const int p = tid >> 3;          // 0..31 position
    const int s = tid & 7;           // 0..7 channel slice
    const int t = t0 + p;
    const int m = b*TT + t;
    const int row = dir ? (b*TT + (t % HS)*HS + (t / HS)) : m;
    const size_t xxbase = (size_t)dir*BTC + (size_t)m*CC;
    const size_t u2base = (size_t)m*128;

    float h[16];
    #pragma unroll
    for (int j = 0; j < 16; ++j) h[j] = 0.0f;

    #pragma unroll 4
    for (int i = 0; i < 16; ++i) {
        const int c = (i*8 + s)*4;
        const float4 xv = ld4(x + (size_t)row*CC + c);
        const float4 xx = ld4(g_xx + xxbase + c);

        #pragma unroll
        for (int v = 0; v < 3; ++v) {
            const float4 mv = ld4(maas + v*CC + c);
            float4 a;
            a.x = fmaf(xx.x, mv.x, xv.x); a.y = fmaf(xx.y, mv.y, xv.y);
            a.z = fmaf(xx.z, mv.z, xv.z); a.w = fmaf(xx.w, mv.w, xv.w);
            uint2 hi, lo; bfsplit4(a, hi, lo);
            const size_t vb = (size_t)(dir*3 + v) * BTC;
            ((uint2*)(g_Ahi + vb))[u2base + c/4] = hi;
            ((uint2*)(g_Alo + vb))[u2base + c/4] = lo;
        }

        const float4 mw = ld4(maas + 3*CC + c);
        const float v0 = fmaf(xx.x, mw.x, xv.x);
        const float v1 = fmaf(xx.y, mw.y, xv.y);
        const float v2 = fmaf(xx.z, mw.z, xv.z);
        const float v3 = fmaf(xx.w, mw.w, xv.w);
        #pragma unroll
        for (int j = 0; j < 16; ++j) {
            const float4 w4 = *(const float4*)(w1s + j*CC + c);
            h[j] = fmaf(v0, w4.x, h[j]);
            h[j] = fmaf(v1, w4.y, h[j]);
            h[j] = fmaf(v2, w4.z, h[j]);
            h[j] = fmaf(v3, w4.w, h[j]);
        }
    }

    #pragma unroll
    for (int j = 0; j < 16; ++j) {
        h[j] += __shfl_xor_sync(0xffffffffu, h[j], 1);
        h[j] += __shfl_xor_sync(0xffffffffu, h[j], 2);
        h[j] += __shfl_xor_sync(0xffffffffu, h[j], 4);
    }
    if (s == 0) {
        #pragma unroll
        for (int j = 0; j < 16; ++j) Hs[p][j] = tanhf(h[j]);
    }
    __syncthreads();

    // stage w2 (already [j][c]) into the same smem buffer
    for (int idx4 = tid; idx4 < 16*CC/4; idx4 += 256)
        ((float4*)w1s)[idx4] = ((const float4*)w2)[idx4];
    __syncthreads();

    // expansion: thread owns 2 channels across all TP positions
    const int c0 = tid*2;
    float w2a[16], w2b[16];
    #pragma unroll
    for (int j = 0; j < 16; ++j) { w2a[j] = w1s[j*CC + c0]; w2b[j] = w1s[j*CC + c0 + 1]; }
    const float td0 = tdec[c0], td1 = tdec[c0+1];
    float* dbase = g_d + (size_t)dir*BTC + (size_t)(b*TT + t0)*CC + c0;
    #pragma unroll 4
    for (int pp = 0; pp < TP; ++pp) {
        float a0 = td0, a1 = td1;
        #pragma unroll
        for (int j = 0; j < 16; ++j) {
            const float hj = Hs[pp][j];
            a0 = fmaf(hj, w2a[j], a0);
            a1 = fmaf(hj, w2b[j], a1);
        }
        *(float2*)(dbase + (size_t)pp*CC) = make_float2(expf(-expf(a0)), expf(-expf(a1)));
    }
}

// ---------------- prep: W -> bf16 hi/lo planes (8 ch/thread) ----------------
__global__ void prep_w_kernel(const float* __restrict__ Wr, const float* __restrict__ Wk,
                              const float* __restrict__ Wv, const float* __restrict__ Wo)
{
    const int idx = blockIdx.x*256 + threadIdx.x;       // over 4*CC*CC/8
    const int w = idx >> 15;                             // CC*CC/8 = 32768
    const int r = idx & 32767;
    const float* W = (w==0) ? Wr : (w==1) ? Wk : (w==2) ? Wv : Wo;
    const float4 va = ld4(W + (size_t)r*8);
    const float4 vb = ld4(W + (size_t)r*8 + 4);
    uint2 ha, la, hb, lb;
    bfsplit4(va, ha, la);
    bfsplit4(vb, hb, lb);
    ((uint4*)(g_Whi + (size_t)w*CC*CC))[r] = make_uint4(ha.x, ha.y, hb.x, hb.y);
    ((uint4*)(g_Wlo + (size_t)w*CC*CC))[r] = make_uint4(la.x, la.y, lb.x, lb.y);
}

// ---------------- bf16-split tensor-core GEMM: Out[m][n] = sum_k A[m][k]*W[n][k] ----------------
#define BKW 8                       // u32 per row per plane (16 bf16)
#define PLANE_W (128*BKW)           // 1024 u32
#define PLANE_B (PLANE_W*4)         // 4096 B
#define STAGE_B (PLANE_B*4)         // 16384 B

__device__ __forceinline__ void cp16(uint32_t dst, const void* src) {
    asm volatile("cp.async.cg.shared.global [%0], [%1], 16;\n" :: "r"(dst), "l"(src));
}
__device__ __forceinline__ void ldsm4(uint32_t* r, uint32_t a) {
    asm volatile("ldmatrix.sync.aligned.m8n8.x4.shared.b16 {%0,%1,%2,%3}, [%4];"
        : "=r"(r[0]), "=r"(r[1]), "=r"(r[2]), "=r"(r[3]) : "r"(a));
}

__global__ __launch_bounds__(256)
void gemm_bf16_kernel(float* __restrict__ Out_ext, int a_sel, int w_sel, int out_sel, int dir)
{
    __shared__ uint32_t sm[3][4][PLANE_W];   // [stage][Ahi,Alo,Bhi,Blo] = 48KB

    const int tid = threadIdx.x;
    const int bn = blockIdx.x * 128;
    const int bm = blockIdx.y * 128;

    const uint16_t* Ah = g_Ahi + (size_t)a_sel*BTC;
    const uint16_t* Al = g_Alo + (size_t)a_sel*BTC;
    const uint16_t* Bh = g_Whi + (size_t)w_sel*CC*CC;
    const uint16_t* Bl = g_Wlo + (size_t)w_sel*CC*CC;
    float* Out;
    switch (out_sel) {
        case 0: Out = g_r + (size_t)dir*BTC; break;
        case 1: Out = g_k + (size_t)dir*BTC; break;
        case 2: Out = g_v + (size_t)dir*BTC; break;
        default: Out = Out_ext; break;
    }

    // ---- staging: one 16B chunk per plane per thread per ktile ----
    const int row  = tid >> 1;
    const int half = tid & 1;
    const int halfsw = half ^ ((row >> 2) & 1);         // XOR swizzle
    const uint16_t* pa_h = Ah + (size_t)(bm + row)*CC + half*8;
    const uint16_t* pa_l = Al + (size_t)(bm + row)*CC + half*8;
    const uint16_t* pb_h = Bh + (size_t)(bn + row)*CC + half*8;
    const uint16_t* pb_l = Bl + (size_t)(bn + row)*CC + half*8;
    const uint32_t smbase = (uint32_t)__cvta_generic_to_shared(&sm[0][0][0]);
    const uint32_t doff = (uint32_t)(row*32 + halfsw*16);

    const int lane = tid & 31;
    const int grp  = lane >> 2;
    const int qid  = lane & 3;
    const int wid  = tid >> 5;
    const int wm   = wid >> 2;
    const int wn   = wid & 3;

    // A ldmatrix lane offsets
    const int selA = lane >> 3;                              // 0..3
    const int rA   = wm*64 + ((selA & 1) << 3) + (lane & 7); // + mt*16 later
    const int hA   = (selA >> 1) ^ ((rA >> 2) & 1);
    const uint32_t offA = (uint32_t)(rA*32 + hA*16);
    // B ldmatrix x4 over an nt pair: lanes 0-15 -> even nt (k halves), 16-31 -> odd nt
    const int rB0  = wn*32 + ((lane >> 4) << 3) + (lane & 7);   // + np*16 later
    const int hB4  = ((lane >> 3) & 1) ^ ((rB0 >> 2) & 1);      // np*16 keeps bit2 of row>>2 invariant
    const uint32_t offB4 = (uint32_t)(rB0*32 + hB4*16);

    float c[4][4][4];
    #pragma unroll
    for (int mt = 0; mt < 4; ++mt)
        #pragma unroll
        for (int nt = 0; nt < 4; ++nt)
            #pragma unroll
            for (int e = 0; e < 4; ++e) c[mt][nt][e] = 0.0f;

    // prologue: prefetch ktiles 0,1 into stages 0,1
    #pragma unroll
    for (int kt = 0; kt < 2; ++kt) {
        const uint32_t d = smbase + kt*STAGE_B + doff;
        const int off = kt*16;
        cp16(d + 0*PLANE_B, pa_h + off);
        cp16(d + 1*PLANE_B, pa_l + off);
        cp16(d + 2*PLANE_B, pb_h + off);
        cp16(d + 3*PLANE_B, pb_l + off);
        asm volatile("cp.async.commit_group;\n");
    }

    int p = 0;
    for (int kt = 0; kt < 32; ++kt) {
        asm volatile("cp.async.wait_group 1;\n");
        __syncthreads();

        const uint32_t sb = smbase + p*STAGE_B;
        uint32_t ah[4][4], al[4][4], bh[4][2], bl[4][2];
        #pragma unroll
        for (int mt = 0; mt < 4; ++mt) ldsm4(ah[mt], sb + 0*PLANE_B + mt*512 + offA);
        #pragma unroll
        for (int mt = 0; mt < 4; ++mt) ldsm4(al[mt], sb + 1*PLANE_B + mt*512 + offA);
        #pragma unroll
        for (int np = 0; np < 2; ++np) {
            uint32_t btmp[4];
            ldsm4(btmp, sb + 2*PLANE_B + np*512 + offB4);
            bh[2*np][0] = btmp[0]; bh[2*np][1] = btmp[1];
            bh[2*np+1][0] = btmp[2]; bh[2*np+1][1] = btmp[3];
            ldsm4(btmp, sb + 3*PLANE_B + np*512 + offB4);
            bl[2*np][0] = btmp[0]; bl[2*np][1] = btmp[1];
            bl[2*np+1][0] = btmp[2]; bl[2*np+1][1] = btmp[3];
        }

        #pragma unroll
        for (int mt = 0; mt < 4; ++mt) {
            #pragma unroll
            for (int nt = 0; nt < 4; ++nt) {
                asm volatile(
                    "mma.sync.aligned.m16n8k16.row.col.f32.bf16.bf16.f32 "
                    "{%0,%1,%2,%3}, {%4,%5,%6,%7}, {%8,%9}, {%0,%1,%2,%3};"
                    : "+f"(c[mt][nt][0]), "+f"(c[mt][nt][1]),
                      "+f"(c[mt][nt][2]), "+f"(c[mt][nt][3])
                    : "r"(ah[mt][0]), "r"(ah[mt][1]), "r"(ah[mt][2]), "r"(ah[mt][3]),
                      "r"(bh[nt][0]), "r"(bh[nt][1]));
                asm volatile(
                    "mma.sync.aligned.m16n8k16.row.col.f32.bf16.bf16.f32 "
                    "{%0,%1,%2,%3}, {%4,%5,%6,%7}, {%8,%9}, {%0,%1,%2,%3};"
                    : "+f"(c[mt][nt][0]), "+f"(c[mt][nt][1]),
                      "+f"(c[mt][nt][2]), "+f"(c[mt][nt][3])
                    : "r"(al[mt][0]), "r"(al[mt][1]), "r"(al[mt][2]), "r"(al[mt][3]),
                      "r"(bh[nt][0]), "r"(bh[nt][1]));
                asm volatile(
                    "mma.sync.aligned.m16n8k16.row.col.f32.bf16.bf16.f32 "
                    "{%0,%1,%2,%3}, {%4,%5,%6,%7}, {%8,%9}, {%0,%1,%2,%3};"
                    : "+f"(c[mt][nt][0]), "+f"(c[mt][nt][1]),
                      "+f"(c[mt][nt][2]), "+f"(c[mt][nt][3])
                    : "r"(ah[mt][0]), "r"(ah[mt][1]), "r"(ah[mt][2]), "r"(ah[mt][3]),
                      "r"(bl[nt][0]), "r"(bl[nt][1]));
            }
        }

        // prefetch ktile kt+2 into the stage consumed at iteration kt-1
        if (kt < 30) {
            int ps = p + 2; if (ps >= 3) ps -= 3;
            const uint32_t d = smbase + ps*STAGE_B + doff;
            const int off = (kt+2)*16;
            cp16(d + 0*PLANE_B, pa_h + off);
            cp16(d + 1*PLANE_B, pa_l + off);
            cp16(d + 2*PLANE_B, pb_h + off);
            cp16(d + 3*PLANE_B, pb_l + off);
        }
        asm volatile("cp.async.commit_group;\n");
        if (++p == 3) p = 0;
    }

    // epilogue
    #pragma unroll
    for (int mt = 0; mt < 4; ++mt) {
        const int rrow = bm + wm*64 + mt*16 + grp;
        #pragma unroll
        for (int nt = 0; nt < 4; ++nt) {
            const int col = bn + wn*32 + nt*8 + qid*2;
            *(float2*)(Out + (size_t)rrow*CC + col)     = make_float2(c[mt][nt][0], c[mt][nt][1]);
            *(float2*)(Out + (size_t)(rrow+8)*CC + col) = make_float2(c[mt][nt][2], c[mt][nt][3]);
        }
    }
}

// ---------------- WKV6 chunked scan ----------------
__global__ void wkv_pass1_kernel()
{
    const int gt = blockIdx.x*128 + threadIdx.x;
    const int s = gt & 15;
    const int j = s & 7, p = s >> 3;
    const int i0 = p*4;
    const int ucid = gt >> 4;
    const int cch = ucid % NCHUNK;
    const int unit = ucid / NCHUNK;
    const int h = unit & 63, b = (unit >> 6) & 7, dir = unit >> 9;

    const size_t base = (size_t)dir*BTC + (size_t)(b*TT + cch*CLEN)*CC + h*NN;
    const float* kk = g_k + base;
    const float* vv = g_v + base;
    const float* dd = g_d + base;

    float S0=0.f,S1=0.f,S2=0.f,S3=0.f, P0=1.f,P1=1.f,P2=1.f,P3=1.f;
    int off = 0;
    #pragma unroll 4
    for (int t = 0; t < CLEN; ++t, off += CC) {
        const float4 k4 = ld4(kk + off + i0);
        const float4 d4 = ld4(dd + off + i0);
        const float v = vv[off + j];
        S0 = fmaf(d4.x, S0, k4.x*v); P0 *= d4.x;
        S1 = fmaf(d4.y, S1, k4.y*v); P1 *= d4.y;
        S2 = fmaf(d4.z, S2, k4.z*v); P2 *= d4.z;
        S3 = fmaf(d4.w, S3, k4.w*v); P3 *= d4.w;
    }
    float* Mp = g_M + (size_t)ucid*64;
    Mp[(i0+0)*8 + j] = S0;
    Mp[(i0+1)*8 + j] = S1;
    Mp[(i0+2)*8 + j] = S2;
    Mp[(i0+3)*8 + j] = S3;
    if (j == 0) {
        float* Pp = g_P + (size_t)ucid*8;
        Pp[i0+0] = P0; Pp[i0+1] = P1; Pp[i0+2] = P2; Pp[i0+3] = P3;
    }
}

__global__ void wkv_pass2_kernel()
{
    const int gt = blockIdx.x*128 + threadIdx.x;   // 16384 threads
    const int s = gt & 15;
    const int j = s & 7, p = s >> 3;
    const int i0 = p*4;
    const int unit = gt >> 4;

    float S0=0.f,S1=0.f,S2=0.f,S3=0.f;
    for (int cch = 0; cch < NCHUNK; ++cch) {
        const size_t uc = (size_t)unit*NCHUNK + cch;
        float* Sp = g_S0 + uc*64;
        Sp[(i0+0)*8 + j] = S0;
        Sp[(i0+1)*8 + j] = S1;
        Sp[(i0+2)*8 + j] = S2;
        Sp[(i0+3)*8 + j] = S3;
        const float* Pp = g_P + uc*8;
        const float* Mp = g_M + uc*64;
        S0 = fmaf(Pp[i0+0], S0, Mp[(i0+0)*8 + j]);
        S1 = fmaf(Pp[i0+1], S1, Mp[(i0+1)*8 + j]);
        S2 = fmaf(Pp[i0+2], S2, Mp[(i0+2)*8 + j]);
        S3 = fmaf(Pp[i0+3], S3, Mp[(i0+3)*8 + j]);
    }
}

__global__ void wkv_pass3_kernel(const float* __restrict__ u)
{
    const int gt = blockIdx.x*128 + threadIdx.x;
    const int s = gt & 15;
    const int j = s & 7, p = s >> 3;
    const int i0 = p*4;
    const int ucid = gt >> 4;
    const int cch = ucid % NCHUNK;
    const int unit = ucid / NCHUNK;
    const int h = unit & 63, b = (unit >> 6) & 7, dir = unit >> 9;

    const float4 uu = ld4(u + h*NN + i0);
    const size_t base = (size_t)dir*BTC + (size_t)(b*TT + cch*CLEN)*CC + h*NN;
    const float* rr = g_r + base;
    const float* kk = g_k + base;
    const float* vv = g_v + base;
    const float* dd = g_d + base;
    float* yy = g_y + base;

    const float* Sp = g_S0 + (size_t)ucid*64;
    float S0 = Sp[(i0+0)*8 + j];
    float S1 = Sp[(i0+1)*8 + j];
    float S2 = Sp[(i0+2)*8 + j];
    float S3 = Sp[(i0+3)*8 + j];

    int off = 0;
    #pragma unroll 2
    for (int t = 0; t < CLEN; ++t, off += CC) {
        const float4 r4 = ld4(rr + off + i0);
        const float4 k4 = ld4(kk + off + i0);
        const float4 d4 = ld4(dd + off + i0);
        const float v = vv[off + j];
        float y = 0.f, kv, tt;
        kv = k4.x*v; tt = fmaf(uu.x, kv, S0); y = fmaf(r4.x, tt, y); S0 = fmaf(d4.x, S0, kv);
        kv = k4.y*v; tt = fmaf(uu.y, kv, S1); y = fmaf(r4.y, tt, y); S1 = fmaf(d4.y, S1, kv);
        kv = k4.z*v; tt = fmaf(uu.z, kv, S2); y = fmaf(r4.z, tt, y); S2 = fmaf(d4.z, S2, kv);
        kv = k4.w*v; tt = fmaf(uu.w, kv, S3); y = fmaf(r4.w, tt, y); S3 = fmaf(d4.w, S3, kv);
        y += __shfl_xor_sync(0xffffffffu, y, 8);
        if (p == 0) yy[off + j] = y;
    }
}

// ---------------- combine directions + layernorm -> bf16 hi/lo planes (slot 6) ----------------
__global__ void combine_ln_kernel(const float* __restrict__ lng,
                                  const float* __restrict__ lnb)
{
    const int t = blockIdx.x, b = blockIdx.y;
    const int tid = threadIdx.x;   // 128
    const int c0 = tid*4;
    const int y = t / HS, xq = t % HS;
    const int tcol = xq*HS + y;
    const int m = b*TT + t;
    const float* yr = g_y + (size_t)m*CC;
    const float* yc = g_y + (size_t)BTC + (size_t)(b*TT + tcol)*CC;

    const float4 va = ld4(yr + c0);
    const float4 vb = ld4(yc + c0);
    float4 o;
    o.x = 0.5f*(va.x + vb.x); o.y = 0.5f*(va.y + vb.y);
    o.z = 0.5f*(va.z + vb.z); o.w = 0.5f*(va.w + vb.w);
    float s  = o.x + o.y + o.z + o.w;
    float sq = o.x*o.x + o.y*o.y + o.z*o.z + o.w*o.w;
    #pragma unroll
    for (int off = 16; off > 0; off >>= 1) {
        s  += __shfl_xor_sync(0xffffffffu, s,  off);
        sq += __shfl_xor_sync(0xffffffffu, sq, off);
    }
    __shared__ float ss[4], sqs[4];
    if ((tid & 31) == 0) { ss[tid >> 5] = s; sqs[tid >> 5] = sq; }
    __syncthreads();
    s  = ss[0] + ss[1] + ss[2] + ss[3];
    sq = sqs[0] + sqs[1] + sqs[2] + sqs[3];
    const float mu = s * (1.0f/CC);
    const float var = sq * (1.0f/CC) - mu*mu;
    const float rstd = rsqrtf(var + 1e-5f);

    const float4 g4 = ld4(lng + c0);
    const float4 b4 = ld4(lnb + c0);
    float4 res;
    res.x = (o.x - mu)*rstd*g4.x + b4.x;
    res.y = (o.y - mu)*rstd*g4.y + b4.y;
    res.z = (o.z - mu)*rstd*g4.z + b4.z;
    res.w = (o.w - mu)*rstd*g4.w + b4.w;
    uint2 hi, lo;
    bfsplit4(res, hi, lo);
    const size_t u2idx = (size_t)m*128 + tid;
    ((uint2*)(g_Ahi + (size_t)6*BTC))[u2idx] = hi;
    ((uint2*)(g_Alo + (size_t)6*BTC))[u2idx] = lo;
}

// ---------------- launch ----------------
extern "C" void kernel_launch(void* const* d_in, const int* in_sizes, int n_in,
                              void* d_out, int out_size)
{
    (void)in_sizes; (void)n_in; (void)out_size;
    const float* x     = (const float*)d_in[0];
    const float* c1    = (const float*)d_in[3];
    const float* c3    = (const float*)d_in[4];
    const float* c5    = (const float*)d_in[5];
    const float* alpha = (const float*)d_in[6];
    const float* maa_w = (const float*)d_in[7];
    const float* maa_k = (const float*)d_in[8];
    const float* maa_v = (const float*)d_in[9];
    const float* maa_r = (const float*)d_in[10];
    const float* tdec  = (const float*)d_in[11];
    const float* w1    = (const float*)d_in[12];
    const float* w2    = (const float*)d_in[13];
    const float* uu    = (const float*)d_in[14];
    const float* Wr    = (const float*)d_in[15];
    const float* Wk    = (const float*)d_in[16];
    const float* Wv    = (const float*)d_in[17];
    const float* Wo    = (const float*)d_in[18];
    const float* lng   = (const float*)d_in[19];
    const float* lnb   = (const float*)d_in[20];

    prep_coef_kernel<<<1, 512>>>(c1, c3, c5, alpha);
    prep_w_kernel<<<(4*CC*CC/8)/256, 256>>>(Wr, Wk, Wv, Wo);
    conv_shift2_kernel<<<dim3(HS, BB, 2), 256>>>(x);
    fused_dp2_kernel<<<dim3(TT/TP, BB, 2), 256>>>(x, maa_w, maa_r, maa_k, maa_v, tdec, w1, w2);

    const dim3 ggrid(CC/128, MM/128);   // (4, 144)
    for (int dir = 0; dir < 2; ++dir) {
        gemm_bf16_kernel<<<ggrid, 256>>>(nullptr, dir*3+0, 0, 0, dir);
        gemm_bf16_kernel<<<ggrid, 256>>>(nullptr, dir*3+1, 1, 1, dir);
        gemm_bf16_kernel<<<ggrid, 256>>>(nullptr, dir*3+2, 2, 2, dir);
    }

    wkv_pass1_kernel<<<(NUNIT*NCHUNK*16)/128, 128>>>();
    wkv_pass2_kernel<<<(NUNIT*16)/128, 128>>>();
    wkv_pass3_kernel<<<(NUNIT*NCHUNK*16)/128, 128>>>(uu);

    combine_ln_kernel<<<dim3(TT, BB), 128>>>(lng, lnb);
    gemm_bf16_kernel<<<ggrid, 256>>>((float*)d_out, 6, 3, 3, 0);
}